// round 1
// baseline (speedup 1.0000x reference)
#include <cuda_runtime.h>
#include <cuda_bf16.h>
#include <math.h>

// Problem constants
#define BATCH   2
#define S_LEN   2048
#define DMODEL  1024
#define NHEAD   16
#define HDIM    64
#define QKVD    (3*DMODEL)     // 3072
#define ROWS    (BATCH*S_LEN)  // 4096

// Scratch (device globals: allocation-free per harness rules)
__device__ float g_x[ROWS * DMODEL];      // layernorm output      16 MB
__device__ float g_qkv[ROWS * QKVD];      // qkv (+rope applied)   48 MB
__device__ float g_ctx[ROWS * DMODEL];    // attention context     16 MB

// ---------------------------------------------------------------------------
// 1) LayerNorm: one block per row (1024 cols), 256 threads, float4 per thread
// ---------------------------------------------------------------------------
__global__ void __launch_bounds__(256) ln_kernel(
    const float* __restrict__ x, const float* __restrict__ gamma,
    const float* __restrict__ beta, float* __restrict__ y)
{
    __shared__ float red_s[8], red_ss[8];
    __shared__ float sh_mean, sh_inv;
    int row = blockIdx.x;
    int tid = threadIdx.x;
    const float4* xr = (const float4*)(x + (size_t)row * DMODEL);
    float4 v = xr[tid];
    float s  = v.x + v.y + v.z + v.w;
    float ss = v.x*v.x + v.y*v.y + v.z*v.z + v.w*v.w;
    #pragma unroll
    for (int off = 16; off > 0; off >>= 1) {
        s  += __shfl_down_sync(0xffffffffu, s,  off);
        ss += __shfl_down_sync(0xffffffffu, ss, off);
    }
    int wid = tid >> 5, lane = tid & 31;
    if (lane == 0) { red_s[wid] = s; red_ss[wid] = ss; }
    __syncthreads();
    if (tid == 0) {
        float S = 0.f, SS = 0.f;
        #pragma unroll
        for (int i = 0; i < 8; ++i) { S += red_s[i]; SS += red_ss[i]; }
        float mean = S * (1.f / DMODEL);
        float var  = SS * (1.f / DMODEL) - mean * mean;
        sh_mean = mean;
        sh_inv  = rsqrtf(var + 1e-5f);
    }
    __syncthreads();
    float mean = sh_mean, inv = sh_inv;
    float4 gv = ((const float4*)gamma)[tid];
    float4 bv = ((const float4*)beta)[tid];
    float4 o;
    o.x = (v.x - mean) * inv * gv.x + bv.x;
    o.y = (v.y - mean) * inv * gv.y + bv.y;
    o.z = (v.z - mean) * inv * gv.z + bv.z;
    o.w = (v.w - mean) * inv * gv.w + bv.w;
    ((float4*)(y + (size_t)row * DMODEL))[tid] = o;
}

// ---------------------------------------------------------------------------
// 2) GEMM: C[M,N] = A[M,K] @ B[N,K]^T + bias[N]
//    64x64 tile, BK=16, 256 threads, 4x4 microtile. M,N % 64 == 0, K % 16 == 0.
// ---------------------------------------------------------------------------
__global__ void __launch_bounds__(256) gemm_nt_kernel(
    const float* __restrict__ A, const float* __restrict__ B,
    const float* __restrict__ bias, float* __restrict__ C,
    int M, int N, int K)
{
    __shared__ __align__(16) float As[16][68];
    __shared__ __align__(16) float Bs[16][68];
    int tid = threadIdx.x;
    int tx = tid & 15, ty = tid >> 4;
    int row0 = blockIdx.y * 64, col0 = blockIdx.x * 64;
    int lr = tid >> 2;             // 0..63
    int lc = (tid & 3) << 2;       // 0,4,8,12
    const float* aptr = A + (size_t)(row0 + lr) * K + lc;
    const float* bptr = B + (size_t)(col0 + lr) * K + lc;
    float acc[4][4];
    #pragma unroll
    for (int i = 0; i < 4; ++i)
        #pragma unroll
        for (int j = 0; j < 4; ++j) acc[i][j] = 0.f;

    for (int k0 = 0; k0 < K; k0 += 16) {
        float4 av = *(const float4*)(aptr + k0);
        float4 bv = *(const float4*)(bptr + k0);
        As[lc+0][lr] = av.x; As[lc+1][lr] = av.y; As[lc+2][lr] = av.z; As[lc+3][lr] = av.w;
        Bs[lc+0][lr] = bv.x; Bs[lc+1][lr] = bv.y; Bs[lc+2][lr] = bv.z; Bs[lc+3][lr] = bv.w;
        __syncthreads();
        #pragma unroll
        for (int k = 0; k < 16; ++k) {
            float4 a4 = *(const float4*)&As[k][ty*4];
            float4 b4 = *(const float4*)&Bs[k][tx*4];
            float ar[4] = {a4.x, a4.y, a4.z, a4.w};
            float br[4] = {b4.x, b4.y, b4.z, b4.w};
            #pragma unroll
            for (int i = 0; i < 4; ++i)
                #pragma unroll
                for (int j = 0; j < 4; ++j)
                    acc[i][j] += ar[i] * br[j];
        }
        __syncthreads();
    }
    #pragma unroll
    for (int i = 0; i < 4; ++i) {
        float* crow = C + (size_t)(row0 + ty*4 + i) * N + col0 + tx*4;
        #pragma unroll
        for (int j = 0; j < 4; ++j)
            crow[j] = acc[i][j] + bias[col0 + tx*4 + j];
    }
}

// ---------------------------------------------------------------------------
// 3) RoPE in-place on q,k halves of g_qkv. One thread per (b,s,h,freq-pair).
//    Angles in double so precision is a non-issue vs 1e-3 threshold.
// ---------------------------------------------------------------------------
__global__ void __launch_bounds__(256) rope_kernel(float* __restrict__ qkv)
{
    int idx = blockIdx.x * 256 + threadIdx.x;   // B*S*H*32 total
    int i  = idx & 31;
    int h  = (idx >> 5) & 15;
    int sb = idx >> 9;                          // b*S + s
    int s  = sb & (S_LEN - 1);
    double inv = pow(10000.0, -(double)(2 * i) / 64.0);
    double ang = (double)s * inv;
    float c  = (float)cos(ang);
    float sn = (float)sin(ang);
    size_t base = (size_t)sb * QKVD + h * (3 * HDIM);
    #pragma unroll
    for (int t = 0; t < 2; ++t) {               // t=0: q, t=1: k
        size_t off = base + t * HDIM;
        float x1 = qkv[off + i];
        float x2 = qkv[off + 32 + i];
        qkv[off + i]      = x1 * c - x2 * sn;
        qkv[off + 32 + i] = x2 * c + x1 * sn;
    }
}

// ---------------------------------------------------------------------------
// 4) Flash-style causal attention. Block = (qt, b*h). 64x64 tiles, HD=64.
//    256 threads: thread t owns row r=t/4; S-phase cols c = tx+4i,
//    O-phase cols d = tx*16..+15. P staged through Ks smem (reused).
//    PAD=68 -> conflict-free (bank = 4r+c mod 32 distinct over a warp).
// ---------------------------------------------------------------------------
#define ATT_PAD 68
#define ATT_SMEM (3 * 64 * ATT_PAD * 4)

__global__ void __launch_bounds__(256) attn_kernel(
    const float* __restrict__ qkv, float* __restrict__ ctx)
{
    extern __shared__ __align__(16) float sm[];
    float* Qs = sm;
    float* Ks = sm + 64 * ATT_PAD;   // reused as P after S-phase
    float* Vs = sm + 2 * 64 * ATT_PAD;

    int qt = blockIdx.x;
    int bh = blockIdx.y;
    int b = bh >> 4, h = bh & 15;
    int tid = threadIdx.x;
    int r  = tid >> 2;     // 0..63
    int tx = tid & 3;      // 0..3
    const float scale = 0.125f;  // 1/sqrt(64)

    size_t base_b = (size_t)b * S_LEN * QKVD;
    int qoff = h * (3 * HDIM);
    int koff = qoff + HDIM;
    int voff = qoff + 2 * HDIM;

    // Load Q tile (pre-scaled)
    {
        int lc = tx * 16;
        const float* src = qkv + base_b + (size_t)(qt*64 + r) * QKVD + qoff + lc;
        float* dst = Qs + r * ATT_PAD + lc;
        #pragma unroll
        for (int j = 0; j < 16; j += 4) {
            float4 v = *(const float4*)(src + j);
            v.x *= scale; v.y *= scale; v.z *= scale; v.w *= scale;
            *(float4*)(dst + j) = v;
        }
    }

    float m_run = -1e30f, l_run = 0.f;
    float o[16];
    #pragma unroll
    for (int j = 0; j < 16; ++j) o[j] = 0.f;

    int nk = qt + 1;
    for (int kt = 0; kt < nk; ++kt) {
        __syncthreads();   // prev-iter P/V reads done (also covers Q store, iter 0)
        {
            int lc = tx * 16;
            const float* ks = qkv + base_b + (size_t)(kt*64 + r) * QKVD + koff + lc;
            const float* vs = qkv + base_b + (size_t)(kt*64 + r) * QKVD + voff + lc;
            float* kd = Ks + r * ATT_PAD + lc;
            float* vd = Vs + r * ATT_PAD + lc;
            #pragma unroll
            for (int j = 0; j < 16; j += 4) {
                *(float4*)(kd + j) = *(const float4*)(ks + j);
                *(float4*)(vd + j) = *(const float4*)(vs + j);
            }
        }
        __syncthreads();

        // S-phase: s[i] = q_row . k_col, c = tx + 4i
        float s[16];
        #pragma unroll
        for (int i = 0; i < 16; ++i) s[i] = 0.f;
        #pragma unroll
        for (int d0 = 0; d0 < 64; d0 += 4) {
            float4 q4 = *(const float4*)(Qs + r * ATT_PAD + d0);
            #pragma unroll
            for (int i = 0; i < 16; ++i) {
                const float4 k4 = *(const float4*)(Ks + (tx + 4*i) * ATT_PAD + d0);
                s[i] += q4.x*k4.x + q4.y*k4.y + q4.z*k4.z + q4.w*k4.w;
            }
        }
        // causal mask
        int qg = qt * 64 + r;
        int kbase = kt * 64;
        if (kbase + 63 > qg) {
            #pragma unroll
            for (int i = 0; i < 16; ++i)
                if (kbase + tx + 4*i > qg) s[i] = -1e30f;
        }
        // online softmax stats (row split across 4 adjacent lanes)
        float mx = s[0];
        #pragma unroll
        for (int i = 1; i < 16; ++i) mx = fmaxf(mx, s[i]);
        mx = fmaxf(mx, __shfl_xor_sync(0xffffffffu, mx, 1));
        mx = fmaxf(mx, __shfl_xor_sync(0xffffffffu, mx, 2));
        float m_new = fmaxf(m_run, mx);
        float corr = __expf(m_run - m_new);
        float psum = 0.f;
        #pragma unroll
        for (int i = 0; i < 16; ++i) { s[i] = __expf(s[i] - m_new); psum += s[i]; }
        psum += __shfl_xor_sync(0xffffffffu, psum, 1);
        psum += __shfl_xor_sync(0xffffffffu, psum, 2);
        l_run = l_run * corr + psum;
        m_run = m_new;
        #pragma unroll
        for (int j = 0; j < 16; ++j) o[j] *= corr;

        __syncthreads();     // everyone done reading Ks
        float* Ps = Ks;
        #pragma unroll
        for (int i = 0; i < 16; ++i) Ps[r * ATT_PAD + tx + 4*i] = s[i];
        __syncthreads();

        // O-phase: o[d] += sum_c P[r][c] * V[c][d], d = tx*16 + 0..15
        #pragma unroll
        for (int c = 0; c < 64; c += 4) {
            float4 p4 = *(const float4*)(Ps + r * ATT_PAD + c);
            #pragma unroll
            for (int j = 0; j < 4; ++j) {
                int d = tx * 16 + j * 4;
                float4 v0 = *(const float4*)(Vs + (c+0) * ATT_PAD + d);
                float4 v1 = *(const float4*)(Vs + (c+1) * ATT_PAD + d);
                float4 v2 = *(const float4*)(Vs + (c+2) * ATT_PAD + d);
                float4 v3 = *(const float4*)(Vs + (c+3) * ATT_PAD + d);
                o[j*4+0] += p4.x*v0.x + p4.y*v1.x + p4.z*v2.x + p4.w*v3.x;
                o[j*4+1] += p4.x*v0.y + p4.y*v1.y + p4.z*v2.y + p4.w*v3.y;
                o[j*4+2] += p4.x*v0.z + p4.y*v1.z + p4.z*v2.z + p4.w*v3.z;
                o[j*4+3] += p4.x*v0.w + p4.y*v1.w + p4.z*v2.w + p4.w*v3.w;
            }
        }
    }

    float invl = 1.f / l_run;
    int qg = qt * 64 + r;
    float* dst = ctx + ((size_t)(b * S_LEN + qg)) * DMODEL + h * HDIM + tx * 16;
    #pragma unroll
    for (int j = 0; j < 4; ++j) {
        float4 v;
        v.x = o[j*4+0] * invl; v.y = o[j*4+1] * invl;
        v.z = o[j*4+2] * invl; v.w = o[j*4+3] * invl;
        *(float4*)(dst + j * 4) = v;
    }
}

// ---------------------------------------------------------------------------
// Launcher
// ---------------------------------------------------------------------------
extern "C" void kernel_launch(void* const* d_in, const int* in_sizes, int n_in,
                              void* d_out, int out_size)
{
    const float* hs     = (const float*)d_in[0];
    const float* gamma  = (const float*)d_in[1];
    const float* beta   = (const float*)d_in[2];
    const float* qkv_w  = (const float*)d_in[3];
    const float* qkv_b  = (const float*)d_in[4];
    const float* proj_w = (const float*)d_in[5];
    const float* proj_b = (const float*)d_in[6];
    float* out = (float*)d_out;

    void *px, *pqkv, *pctx;
    cudaGetSymbolAddress(&px,   g_x);
    cudaGetSymbolAddress(&pqkv, g_qkv);
    cudaGetSymbolAddress(&pctx, g_ctx);
    float* x_s   = (float*)px;
    float* qkv_s = (float*)pqkv;
    float* ctx_s = (float*)pctx;

    // 1) LayerNorm
    ln_kernel<<<ROWS, 256>>>(hs, gamma, beta, x_s);

    // 2) QKV GEMM: [4096,3072] = x[4096,1024] @ W[3072,1024]^T + b
    gemm_nt_kernel<<<dim3(QKVD/64, ROWS/64), 256>>>(x_s, qkv_w, qkv_b, qkv_s,
                                                    ROWS, QKVD, DMODEL);

    // 3) RoPE on q,k halves
    rope_kernel<<<(BATCH*S_LEN*NHEAD*32)/256, 256>>>(qkv_s);

    // 4) Causal attention
    cudaFuncSetAttribute(attn_kernel, cudaFuncAttributeMaxDynamicSharedMemorySize,
                         ATT_SMEM);
    attn_kernel<<<dim3(S_LEN/64, BATCH*NHEAD), 256, ATT_SMEM>>>(qkv_s, ctx_s);

    // 5) Output projection: [4096,1024] = ctx @ Wp[1024,1024]^T + bp
    gemm_nt_kernel<<<dim3(DMODEL/64, ROWS/64), 256>>>(ctx_s, proj_w, proj_b, out,
                                                      ROWS, DMODEL, DMODEL);
}

// round 2
// speedup vs baseline: 1.3014x; 1.3014x over previous
#include <cuda_runtime.h>
#include <cuda_bf16.h>
#include <math.h>
#include <stdint.h>

// Problem constants
#define BATCH   2
#define S_LEN   2048
#define DMODEL  1024
#define NHEAD   16
#define HDIM    64
#define QKVD    (3*DMODEL)     // 3072
#define ROWS    (BATCH*S_LEN)  // 4096

// fp32 scratch
__device__ float g_x[ROWS * DMODEL];      // layernorm output
__device__ float g_qkv[ROWS * QKVD];      // qkv (+rope applied)
__device__ float g_ctx[ROWS * DMODEL];    // attention context

// split-bf16 scratch (ushort to avoid any ctor issues on device globals)
__device__ unsigned short g_xh[ROWS * DMODEL],   g_xl[ROWS * DMODEL];
__device__ unsigned short g_wqh[QKVD * DMODEL],  g_wql[QKVD * DMODEL];
__device__ unsigned short g_wph[DMODEL * DMODEL],g_wpl[DMODEL * DMODEL];
__device__ unsigned short g_ch[ROWS * DMODEL],   g_cl[ROWS * DMODEL];

// ---------------------------------------------------------------------------
// 1) LayerNorm: one block per row (1024 cols), 256 threads, float4 per thread
// ---------------------------------------------------------------------------
__global__ void __launch_bounds__(256) ln_kernel(
    const float* __restrict__ x, const float* __restrict__ gamma,
    const float* __restrict__ beta, float* __restrict__ y)
{
    __shared__ float red_s[8], red_ss[8];
    __shared__ float sh_mean, sh_inv;
    int row = blockIdx.x;
    int tid = threadIdx.x;
    const float4* xr = (const float4*)(x + (size_t)row * DMODEL);
    float4 v = xr[tid];
    float s  = v.x + v.y + v.z + v.w;
    float ss = v.x*v.x + v.y*v.y + v.z*v.z + v.w*v.w;
    #pragma unroll
    for (int off = 16; off > 0; off >>= 1) {
        s  += __shfl_down_sync(0xffffffffu, s,  off);
        ss += __shfl_down_sync(0xffffffffu, ss, off);
    }
    int wid = tid >> 5, lane = tid & 31;
    if (lane == 0) { red_s[wid] = s; red_ss[wid] = ss; }
    __syncthreads();
    if (tid == 0) {
        float S = 0.f, SS = 0.f;
        #pragma unroll
        for (int i = 0; i < 8; ++i) { S += red_s[i]; SS += red_ss[i]; }
        float mean = S * (1.f / DMODEL);
        float var  = SS * (1.f / DMODEL) - mean * mean;
        sh_mean = mean;
        sh_inv  = rsqrtf(var + 1e-5f);
    }
    __syncthreads();
    float mean = sh_mean, inv = sh_inv;
    float4 gv = ((const float4*)gamma)[tid];
    float4 bv = ((const float4*)beta)[tid];
    float4 o;
    o.x = (v.x - mean) * inv * gv.x + bv.x;
    o.y = (v.y - mean) * inv * gv.y + bv.y;
    o.z = (v.z - mean) * inv * gv.z + bv.z;
    o.w = (v.w - mean) * inv * gv.w + bv.w;
    ((float4*)(y + (size_t)row * DMODEL))[tid] = o;
}

// ---------------------------------------------------------------------------
// Split fp32 -> (hi bf16, lo bf16), 4 elements/thread
// ---------------------------------------------------------------------------
__device__ __forceinline__ uint32_t pack_bf2(__nv_bfloat16 a, __nv_bfloat16 b) {
    __nv_bfloat162 t(a, b);
    return *reinterpret_cast<uint32_t*>(&t);
}

__global__ void __launch_bounds__(256) split_bf16_kernel(
    const float* __restrict__ x, unsigned short* __restrict__ hi,
    unsigned short* __restrict__ lo, int n4)
{
    int i = blockIdx.x * 256 + threadIdx.x;
    if (i >= n4) return;
    float4 v = ((const float4*)x)[i];
    __nv_bfloat16 h0 = __float2bfloat16_rn(v.x);
    __nv_bfloat16 h1 = __float2bfloat16_rn(v.y);
    __nv_bfloat16 h2 = __float2bfloat16_rn(v.z);
    __nv_bfloat16 h3 = __float2bfloat16_rn(v.w);
    __nv_bfloat16 l0 = __float2bfloat16_rn(v.x - __bfloat162float(h0));
    __nv_bfloat16 l1 = __float2bfloat16_rn(v.y - __bfloat162float(h1));
    __nv_bfloat16 l2 = __float2bfloat16_rn(v.z - __bfloat162float(h2));
    __nv_bfloat16 l3 = __float2bfloat16_rn(v.w - __bfloat162float(h3));
    uint2 hv = make_uint2(pack_bf2(h0, h1), pack_bf2(h2, h3));
    uint2 lv = make_uint2(pack_bf2(l0, l1), pack_bf2(l2, l3));
    *(uint2*)(hi + (size_t)i * 4) = hv;
    *(uint2*)(lo + (size_t)i * 4) = lv;
}

// ---------------------------------------------------------------------------
// 2) Tensor-core GEMM: C[M,N] = A[M,K] @ B[N,K]^T + bias, split-bf16 x3 MMA.
//    Block 128x128, 8 warps (2x4), warp tile 64x32, m16n8k16 fragments
//    loaded straight from global (K-contiguous rows for both A and B).
// ---------------------------------------------------------------------------
__device__ __forceinline__ void mma_bf16(float* c, const uint32_t* a, const uint32_t* b) {
    asm volatile(
        "mma.sync.aligned.m16n8k16.row.col.f32.bf16.bf16.f32 "
        "{%0,%1,%2,%3}, {%4,%5,%6,%7}, {%8,%9}, {%0,%1,%2,%3};\n"
        : "+f"(c[0]), "+f"(c[1]), "+f"(c[2]), "+f"(c[3])
        : "r"(a[0]), "r"(a[1]), "r"(a[2]), "r"(a[3]), "r"(b[0]), "r"(b[1]));
}

__global__ void __launch_bounds__(256) mma_gemm_nt(
    const unsigned short* __restrict__ Ahu, const unsigned short* __restrict__ Alu,
    const unsigned short* __restrict__ Bhu, const unsigned short* __restrict__ Blu,
    const float* __restrict__ bias, float* __restrict__ C,
    int M, int N, int K)
{
    int wid  = threadIdx.x >> 5, lane = threadIdx.x & 31;
    int wm   = wid >> 2, wn = wid & 3;                // 2 x 4 warps
    int mbase = blockIdx.y * 128 + wm * 64;
    int nbase = blockIdx.x * 128 + wn * 32;
    int g = lane >> 2, q = lane & 3;

    float acc[4][4][4];
    #pragma unroll
    for (int mt = 0; mt < 4; ++mt)
        #pragma unroll
        for (int nt = 0; nt < 4; ++nt)
            #pragma unroll
            for (int e = 0; e < 4; ++e) acc[mt][nt][e] = 0.f;

    for (int k0 = 0; k0 < K; k0 += 16) {
        uint32_t ah[4][4], al[4][4];
        #pragma unroll
        for (int mt = 0; mt < 4; ++mt) {
            size_t off = (size_t)(mbase + mt * 16 + g) * K + k0 + q * 2;
            const unsigned short* p  = Ahu + off;
            const unsigned short* pl = Alu + off;
            ah[mt][0] = *(const uint32_t*)(p);
            ah[mt][1] = *(const uint32_t*)(p + 8 * (size_t)K);
            ah[mt][2] = *(const uint32_t*)(p + 8);
            ah[mt][3] = *(const uint32_t*)(p + 8 * (size_t)K + 8);
            al[mt][0] = *(const uint32_t*)(pl);
            al[mt][1] = *(const uint32_t*)(pl + 8 * (size_t)K);
            al[mt][2] = *(const uint32_t*)(pl + 8);
            al[mt][3] = *(const uint32_t*)(pl + 8 * (size_t)K + 8);
        }
        #pragma unroll
        for (int nt = 0; nt < 4; ++nt) {
            size_t off = (size_t)(nbase + nt * 8 + g) * K + k0 + q * 2;
            const unsigned short* p  = Bhu + off;
            const unsigned short* pl = Blu + off;
            uint32_t bh[2], bl[2];
            bh[0] = *(const uint32_t*)(p);
            bh[1] = *(const uint32_t*)(p + 8);
            bl[0] = *(const uint32_t*)(pl);
            bl[1] = *(const uint32_t*)(pl + 8);
            #pragma unroll
            for (int mt = 0; mt < 4; ++mt) {
                mma_bf16(acc[mt][nt], ah[mt], bh);
                mma_bf16(acc[mt][nt], ah[mt], bl);
                mma_bf16(acc[mt][nt], al[mt], bh);
            }
        }
    }

    #pragma unroll
    for (int mt = 0; mt < 4; ++mt) {
        #pragma unroll
        for (int nt = 0; nt < 4; ++nt) {
            int r = mbase + mt * 16 + g;
            int c = nbase + nt * 8 + q * 2;
            float b0 = bias[c], b1 = bias[c + 1];
            float2 v0; v0.x = acc[mt][nt][0] + b0; v0.y = acc[mt][nt][1] + b1;
            float2 v1; v1.x = acc[mt][nt][2] + b0; v1.y = acc[mt][nt][3] + b1;
            *(float2*)(C + (size_t)r * N + c)       = v0;
            *(float2*)(C + (size_t)(r + 8) * N + c) = v1;
        }
    }
}

// ---------------------------------------------------------------------------
// 3) RoPE in-place on q,k halves of g_qkv (double-precision angles).
// ---------------------------------------------------------------------------
__global__ void __launch_bounds__(256) rope_kernel(float* __restrict__ qkv)
{
    int idx = blockIdx.x * 256 + threadIdx.x;   // B*S*H*32 total
    int i  = idx & 31;
    int h  = (idx >> 5) & 15;
    int sb = idx >> 9;                          // b*S + s
    int s  = sb & (S_LEN - 1);
    double inv = pow(10000.0, -(double)(2 * i) / 64.0);
    double ang = (double)s * inv;
    float c  = (float)cos(ang);
    float sn = (float)sin(ang);
    size_t base = (size_t)sb * QKVD + h * (3 * HDIM);
    #pragma unroll
    for (int t = 0; t < 2; ++t) {               // t=0: q, t=1: k
        size_t off = base + t * HDIM;
        float x1 = qkv[off + i];
        float x2 = qkv[off + 32 + i];
        qkv[off + i]      = x1 * c - x2 * sn;
        qkv[off + 32 + i] = x2 * c + x1 * sn;
    }
}

// ---------------------------------------------------------------------------
// 4) Flash-style causal attention, 128 q-rows x 64 k-cols per block.
//    256 threads: thread t owns rows r=t/4 and r+64; tx = t%4.
//    S-phase cols c = tx+4i; O-phase cols d = tx*16..+15.
//    PAD=68 keeps every tile access <=4-distinct-address + broadcast.
// ---------------------------------------------------------------------------
#define ATT_PAD 68
#define ATT_SMEM ((128 + 64 + 64 + 128) * ATT_PAD * 4)

__global__ void __launch_bounds__(256) attn_kernel(
    const float* __restrict__ qkv, float* __restrict__ ctx)
{
    extern __shared__ __align__(16) float sm[];
    float* Qs = sm;                       // 128 rows
    float* Ks = Qs + 128 * ATT_PAD;       // 64 rows
    float* Vs = Ks + 64 * ATT_PAD;        // 64 rows
    float* Ps = Vs + 64 * ATT_PAD;        // 128 rows

    int qt = blockIdx.x;
    int bh = blockIdx.y;
    int b = bh >> 4, h = bh & 15;
    int tid = threadIdx.x;
    int r  = tid >> 2;     // 0..63
    int tx = tid & 3;      // 0..3
    int lc = tx * 16;
    const float scale = 0.125f;  // 1/sqrt(64)

    size_t base_b = (size_t)b * S_LEN * QKVD;
    int qoff = h * (3 * HDIM);
    int koff = qoff + HDIM;
    int voff = qoff + 2 * HDIM;

    // Load Q tile: 2 rows per thread, pre-scaled
    #pragma unroll
    for (int t = 0; t < 2; ++t) {
        int row = r + t * 64;
        const float* src = qkv + base_b + (size_t)(qt * 128 + row) * QKVD + qoff + lc;
        float* dst = Qs + row * ATT_PAD + lc;
        #pragma unroll
        for (int j = 0; j < 16; j += 4) {
            float4 v = *(const float4*)(src + j);
            v.x *= scale; v.y *= scale; v.z *= scale; v.w *= scale;
            *(float4*)(dst + j) = v;
        }
    }

    float mA = -1e30f, lA = 0.f, mB = -1e30f, lB = 0.f;
    float oA[16], oB[16];
    #pragma unroll
    for (int j = 0; j < 16; ++j) { oA[j] = 0.f; oB[j] = 0.f; }

    int qgA = qt * 128 + r;
    int qgB = qgA + 64;
    int nk = 2 * qt + 2;

    for (int kt = 0; kt < nk; ++kt) {
        __syncthreads();   // prev-iter P/V reads done (also covers Q store, iter 0)
        {
            const float* ks = qkv + base_b + (size_t)(kt * 64 + r) * QKVD + koff + lc;
            const float* vs = qkv + base_b + (size_t)(kt * 64 + r) * QKVD + voff + lc;
            float* kd = Ks + r * ATT_PAD + lc;
            float* vd = Vs + r * ATT_PAD + lc;
            #pragma unroll
            for (int j = 0; j < 16; j += 4) {
                *(float4*)(kd + j) = *(const float4*)(ks + j);
                *(float4*)(vd + j) = *(const float4*)(vs + j);
            }
        }
        __syncthreads();

        // S-phase: s[i] = q_row . k_col, c = tx + 4i, two rows per thread
        float sA[16], sB[16];
        #pragma unroll
        for (int i = 0; i < 16; ++i) { sA[i] = 0.f; sB[i] = 0.f; }
        #pragma unroll
        for (int d0 = 0; d0 < 64; d0 += 4) {
            float4 qa = *(const float4*)(Qs + r * ATT_PAD + d0);
            float4 qb = *(const float4*)(Qs + (r + 64) * ATT_PAD + d0);
            #pragma unroll
            for (int i = 0; i < 16; ++i) {
                const float4 k4 = *(const float4*)(Ks + (tx + 4 * i) * ATT_PAD + d0);
                sA[i] += qa.x * k4.x + qa.y * k4.y + qa.z * k4.z + qa.w * k4.w;
                sB[i] += qb.x * k4.x + qb.y * k4.y + qb.z * k4.z + qb.w * k4.w;
            }
        }
        // causal mask
        int kbase = kt * 64;
        if (kbase + 63 > qgA) {
            #pragma unroll
            for (int i = 0; i < 16; ++i)
                if (kbase + tx + 4 * i > qgA) sA[i] = -1e30f;
        }
        if (kbase + 63 > qgB) {
            #pragma unroll
            for (int i = 0; i < 16; ++i)
                if (kbase + tx + 4 * i > qgB) sB[i] = -1e30f;
        }
        // online softmax (rows split across 4 adjacent lanes)
        {
            float mx = sA[0];
            #pragma unroll
            for (int i = 1; i < 16; ++i) mx = fmaxf(mx, sA[i]);
            mx = fmaxf(mx, __shfl_xor_sync(0xffffffffu, mx, 1));
            mx = fmaxf(mx, __shfl_xor_sync(0xffffffffu, mx, 2));
            float m_new = fmaxf(mA, mx);
            float corr = __expf(mA - m_new);
            float psum = 0.f;
            #pragma unroll
            for (int i = 0; i < 16; ++i) { sA[i] = __expf(sA[i] - m_new); psum += sA[i]; }
            psum += __shfl_xor_sync(0xffffffffu, psum, 1);
            psum += __shfl_xor_sync(0xffffffffu, psum, 2);
            lA = lA * corr + psum;
            mA = m_new;
            #pragma unroll
            for (int j = 0; j < 16; ++j) oA[j] *= corr;
        }
        {
            float mx = sB[0];
            #pragma unroll
            for (int i = 1; i < 16; ++i) mx = fmaxf(mx, sB[i]);
            mx = fmaxf(mx, __shfl_xor_sync(0xffffffffu, mx, 1));
            mx = fmaxf(mx, __shfl_xor_sync(0xffffffffu, mx, 2));
            float m_new = fmaxf(mB, mx);
            float corr = __expf(mB - m_new);
            float psum = 0.f;
            #pragma unroll
            for (int i = 0; i < 16; ++i) { sB[i] = __expf(sB[i] - m_new); psum += sB[i]; }
            psum += __shfl_xor_sync(0xffffffffu, psum, 1);
            psum += __shfl_xor_sync(0xffffffffu, psum, 2);
            lB = lB * corr + psum;
            mB = m_new;
            #pragma unroll
            for (int j = 0; j < 16; ++j) oB[j] *= corr;
        }

        // write P tiles (own buffer; prior reads covered by top-of-loop sync)
        #pragma unroll
        for (int i = 0; i < 16; ++i) {
            Ps[r * ATT_PAD + tx + 4 * i]        = sA[i];
            Ps[(r + 64) * ATT_PAD + tx + 4 * i] = sB[i];
        }
        __syncthreads();

        // O-phase: o[d] += sum_c P[row][c] * V[c][d], d = tx*16 + 0..15
        #pragma unroll
        for (int c = 0; c < 64; c += 4) {
            float4 pa = *(const float4*)(Ps + r * ATT_PAD + c);
            float4 pb = *(const float4*)(Ps + (r + 64) * ATT_PAD + c);
            #pragma unroll
            for (int j = 0; j < 4; ++j) {
                int d = lc + j * 4;
                float4 v0 = *(const float4*)(Vs + (c + 0) * ATT_PAD + d);
                float4 v1 = *(const float4*)(Vs + (c + 1) * ATT_PAD + d);
                float4 v2 = *(const float4*)(Vs + (c + 2) * ATT_PAD + d);
                float4 v3 = *(const float4*)(Vs + (c + 3) * ATT_PAD + d);
                oA[j*4+0] += pa.x*v0.x + pa.y*v1.x + pa.z*v2.x + pa.w*v3.x;
                oA[j*4+1] += pa.x*v0.y + pa.y*v1.y + pa.z*v2.y + pa.w*v3.y;
                oA[j*4+2] += pa.x*v0.z + pa.y*v1.z + pa.z*v2.z + pa.w*v3.z;
                oA[j*4+3] += pa.x*v0.w + pa.y*v1.w + pa.z*v2.w + pa.w*v3.w;
                oB[j*4+0] += pb.x*v0.x + pb.y*v1.x + pb.z*v2.x + pb.w*v3.x;
                oB[j*4+1] += pb.x*v0.y + pb.y*v1.y + pb.z*v2.y + pb.w*v3.y;
                oB[j*4+2] += pb.x*v0.z + pb.y*v1.z + pb.z*v2.z + pb.w*v3.z;
                oB[j*4+3] += pb.x*v0.w + pb.y*v1.w + pb.z*v2.w + pb.w*v3.w;
            }
        }
    }

    float invA = 1.f / lA;
    float invB = 1.f / lB;
    float* dstA = ctx + ((size_t)(b * S_LEN + qgA)) * DMODEL + h * HDIM + lc;
    float* dstB = ctx + ((size_t)(b * S_LEN + qgB)) * DMODEL + h * HDIM + lc;
    #pragma unroll
    for (int j = 0; j < 4; ++j) {
        float4 va, vb;
        va.x = oA[j*4+0]*invA; va.y = oA[j*4+1]*invA;
        va.z = oA[j*4+2]*invA; va.w = oA[j*4+3]*invA;
        vb.x = oB[j*4+0]*invB; vb.y = oB[j*4+1]*invB;
        vb.z = oB[j*4+2]*invB; vb.w = oB[j*4+3]*invB;
        *(float4*)(dstA + j * 4) = va;
        *(float4*)(dstB + j * 4) = vb;
    }
}

// ---------------------------------------------------------------------------
// Launcher
// ---------------------------------------------------------------------------
extern "C" void kernel_launch(void* const* d_in, const int* in_sizes, int n_in,
                              void* d_out, int out_size)
{
    const float* hs     = (const float*)d_in[0];
    const float* gamma  = (const float*)d_in[1];
    const float* beta   = (const float*)d_in[2];
    const float* qkv_w  = (const float*)d_in[3];
    const float* qkv_b  = (const float*)d_in[4];
    const float* proj_w = (const float*)d_in[5];
    const float* proj_b = (const float*)d_in[6];
    float* out = (float*)d_out;

    void *px, *pqkv, *pctx;
    void *pxh, *pxl, *pwqh, *pwql, *pwph, *pwpl, *pch, *pcl;
    cudaGetSymbolAddress(&px,   g_x);
    cudaGetSymbolAddress(&pqkv, g_qkv);
    cudaGetSymbolAddress(&pctx, g_ctx);
    cudaGetSymbolAddress(&pxh,  g_xh);  cudaGetSymbolAddress(&pxl,  g_xl);
    cudaGetSymbolAddress(&pwqh, g_wqh); cudaGetSymbolAddress(&pwql, g_wql);
    cudaGetSymbolAddress(&pwph, g_wph); cudaGetSymbolAddress(&pwpl, g_wpl);
    cudaGetSymbolAddress(&pch,  g_ch);  cudaGetSymbolAddress(&pcl,  g_cl);

    float* x_s   = (float*)px;
    float* qkv_s = (float*)pqkv;
    float* ctx_s = (float*)pctx;

    // 1) LayerNorm
    ln_kernel<<<ROWS, 256>>>(hs, gamma, beta, x_s);

    // Split conversions (x and qkv weights)
    split_bf16_kernel<<<(ROWS*DMODEL/4)/256, 256>>>(x_s, (unsigned short*)pxh,
                                                    (unsigned short*)pxl, ROWS*DMODEL/4);
    split_bf16_kernel<<<(QKVD*DMODEL/4)/256, 256>>>(qkv_w, (unsigned short*)pwqh,
                                                    (unsigned short*)pwql, QKVD*DMODEL/4);

    // 2) QKV GEMM on tensor cores: [4096,3072] = x @ Wq^T + b
    mma_gemm_nt<<<dim3(QKVD/128, ROWS/128), 256>>>(
        (unsigned short*)pxh, (unsigned short*)pxl,
        (unsigned short*)pwqh, (unsigned short*)pwql,
        qkv_b, qkv_s, ROWS, QKVD, DMODEL);

    // 3) RoPE on q,k halves
    rope_kernel<<<(BATCH*S_LEN*NHEAD*32)/256, 256>>>(qkv_s);

    // 4) Causal attention (128 q-rows per block)
    cudaFuncSetAttribute(attn_kernel, cudaFuncAttributeMaxDynamicSharedMemorySize,
                         ATT_SMEM);
    attn_kernel<<<dim3(S_LEN/128, BATCH*NHEAD), 256, ATT_SMEM>>>(qkv_s, ctx_s);

    // Split conversions (ctx and proj weights)
    split_bf16_kernel<<<(ROWS*DMODEL/4)/256, 256>>>(ctx_s, (unsigned short*)pch,
                                                    (unsigned short*)pcl, ROWS*DMODEL/4);
    split_bf16_kernel<<<(DMODEL*DMODEL/4)/256, 256>>>(proj_w, (unsigned short*)pwph,
                                                      (unsigned short*)pwpl, DMODEL*DMODEL/4);

    // 5) Output projection on tensor cores: [4096,1024] = ctx @ Wp^T + bp
    mma_gemm_nt<<<dim3(DMODEL/128, ROWS/128), 256>>>(
        (unsigned short*)pch, (unsigned short*)pcl,
        (unsigned short*)pwph, (unsigned short*)pwpl,
        proj_b, out, ROWS, DMODEL, DMODEL);
}

// round 3
// speedup vs baseline: 5.1133x; 3.9291x over previous
#include <cuda_runtime.h>
#include <cuda_bf16.h>
#include <math.h>
#include <stdint.h>

// Problem constants
#define BATCH   2
#define S_LEN   2048
#define DMODEL  1024
#define NHEAD   16
#define HDIM    64
#define QKVD    (3*DMODEL)     // 3072
#define ROWS    (BATCH*S_LEN)  // 4096
#define BH      (BATCH*NHEAD)  // 32

// Scratch (device globals: allocation-free per harness rules)
__device__ float g_qkv[ROWS * QKVD];                       // qkv fp32 (pre-rope)
__device__ unsigned short g_xh[ROWS * DMODEL],   g_xl[ROWS * DMODEL];
__device__ unsigned short g_wqh[QKVD * DMODEL],  g_wql[QKVD * DMODEL];
__device__ unsigned short g_wph[DMODEL * DMODEL],g_wpl[DMODEL * DMODEL];
__device__ unsigned short g_ch[ROWS * DMODEL],   g_cl[ROWS * DMODEL];
// head-major bf16 split q/k (post-rope) and transposed v
__device__ unsigned short g_qhh[BH * S_LEN * HDIM], g_qll[BH * S_LEN * HDIM];
__device__ unsigned short g_khh[BH * S_LEN * HDIM], g_kll[BH * S_LEN * HDIM];
__device__ unsigned short g_vth[BH * HDIM * S_LEN], g_vtl[BH * HDIM * S_LEN];

// ---------------------------------------------------------------------------
// helpers
// ---------------------------------------------------------------------------
__device__ __forceinline__ uint32_t f2bf2(float lo, float hi) {
    __nv_bfloat162 t = __floats2bfloat162_rn(lo, hi);
    return *reinterpret_cast<uint32_t*>(&t);
}
__device__ __forceinline__ uint32_t sptr(const void* p) {
    return (uint32_t)__cvta_generic_to_shared(p);
}
__device__ __forceinline__ void cp16(void* dst, const void* src) {
    asm volatile("cp.async.cg.shared.global [%0], [%1], 16;\n"
                 :: "r"(sptr(dst)), "l"(src));
}
__device__ __forceinline__ void cp_commit() { asm volatile("cp.async.commit_group;\n"); }
__device__ __forceinline__ void cp_wait0()  { asm volatile("cp.async.wait_group 0;\n"); }
__device__ __forceinline__ void cp_wait1()  { asm volatile("cp.async.wait_group 1;\n"); }

__device__ __forceinline__ void ldsm4(uint32_t* r, const void* p) {
    asm volatile("ldmatrix.sync.aligned.m8n8.x4.shared.b16 {%0,%1,%2,%3}, [%4];\n"
                 : "=r"(r[0]), "=r"(r[1]), "=r"(r[2]), "=r"(r[3]) : "r"(sptr(p)));
}
__device__ __forceinline__ void mma_bf16(float* c, const uint32_t* a, const uint32_t* b) {
    asm volatile(
        "mma.sync.aligned.m16n8k16.row.col.f32.bf16.bf16.f32 "
        "{%0,%1,%2,%3}, {%4,%5,%6,%7}, {%8,%9}, {%0,%1,%2,%3};\n"
        : "+f"(c[0]), "+f"(c[1]), "+f"(c[2]), "+f"(c[3])
        : "r"(a[0]), "r"(a[1]), "r"(a[2]), "r"(a[3]), "r"(b[0]), "r"(b[1]));
}

// ---------------------------------------------------------------------------
// 1) LayerNorm fused with split-bf16 output
// ---------------------------------------------------------------------------
__global__ void __launch_bounds__(256) ln_split_kernel(
    const float* __restrict__ x, const float* __restrict__ gamma,
    const float* __restrict__ beta, unsigned short* __restrict__ yh,
    unsigned short* __restrict__ yl)
{
    __shared__ float red_s[8], red_ss[8];
    __shared__ float sh_mean, sh_inv;
    int row = blockIdx.x;
    int tid = threadIdx.x;
    const float4* xr = (const float4*)(x + (size_t)row * DMODEL);
    float4 v = xr[tid];
    float s  = v.x + v.y + v.z + v.w;
    float ss = v.x*v.x + v.y*v.y + v.z*v.z + v.w*v.w;
    #pragma unroll
    for (int off = 16; off > 0; off >>= 1) {
        s  += __shfl_down_sync(0xffffffffu, s,  off);
        ss += __shfl_down_sync(0xffffffffu, ss, off);
    }
    int wid = tid >> 5, lane = tid & 31;
    if (lane == 0) { red_s[wid] = s; red_ss[wid] = ss; }
    __syncthreads();
    if (tid == 0) {
        float S = 0.f, SS = 0.f;
        #pragma unroll
        for (int i = 0; i < 8; ++i) { S += red_s[i]; SS += red_ss[i]; }
        float mean = S * (1.f / DMODEL);
        float var  = SS * (1.f / DMODEL) - mean * mean;
        sh_mean = mean;
        sh_inv  = rsqrtf(var + 1e-5f);
    }
    __syncthreads();
    float mean = sh_mean, inv = sh_inv;
    float4 gv = ((const float4*)gamma)[tid];
    float4 bv = ((const float4*)beta)[tid];
    float o0 = (v.x - mean) * inv * gv.x + bv.x;
    float o1 = (v.y - mean) * inv * gv.y + bv.y;
    float o2 = (v.z - mean) * inv * gv.z + bv.z;
    float o3 = (v.w - mean) * inv * gv.w + bv.w;
    float h0 = __bfloat162float(__float2bfloat16_rn(o0));
    float h1 = __bfloat162float(__float2bfloat16_rn(o1));
    float h2 = __bfloat162float(__float2bfloat16_rn(o2));
    float h3 = __bfloat162float(__float2bfloat16_rn(o3));
    uint2 hv = make_uint2(f2bf2(h0, h1), f2bf2(h2, h3));
    uint2 lv = make_uint2(f2bf2(o0 - h0, o1 - h1), f2bf2(o2 - h2, o3 - h3));
    *(uint2*)(yh + (size_t)row * DMODEL + tid * 4) = hv;
    *(uint2*)(yl + (size_t)row * DMODEL + tid * 4) = lv;
}

// ---------------------------------------------------------------------------
// split fp32 -> (hi, lo) bf16, 4 elements/thread (weights)
// ---------------------------------------------------------------------------
__global__ void __launch_bounds__(256) split_bf16_kernel(
    const float* __restrict__ x, unsigned short* __restrict__ hi,
    unsigned short* __restrict__ lo, int n4)
{
    int i = blockIdx.x * 256 + threadIdx.x;
    if (i >= n4) return;
    float4 v = ((const float4*)x)[i];
    float h0 = __bfloat162float(__float2bfloat16_rn(v.x));
    float h1 = __bfloat162float(__float2bfloat16_rn(v.y));
    float h2 = __bfloat162float(__float2bfloat16_rn(v.z));
    float h3 = __bfloat162float(__float2bfloat16_rn(v.w));
    uint2 hv = make_uint2(f2bf2(h0, h1), f2bf2(h2, h3));
    uint2 lv = make_uint2(f2bf2(v.x - h0, v.y - h1), f2bf2(v.z - h2, v.w - h3));
    *(uint2*)(hi + (size_t)i * 4) = hv;
    *(uint2*)(lo + (size_t)i * 4) = lv;
}

// ---------------------------------------------------------------------------
// 2) Smem-staged double-buffered split-bf16 MMA GEMM.
//    C[M,N] = A[M,K] @ B[N,K]^T + bias.
//    Block 128x128, BK=32, 8 warps (2x4), warp 64x32.
//    Smem rows padded to 40 bf16 (20 words) -> conflict-free LDSM/cp.async.
// ---------------------------------------------------------------------------
#define GPAD 40
#define GTILE (128 * GPAD)            // ushorts per tile
#define GSTAGE (4 * GTILE)            // Ah,Al,Bh,Bl
#define GEMM_SMEM (2 * GSTAGE * 2)    // bytes

__global__ void __launch_bounds__(256) mma_gemm_smem(
    const unsigned short* __restrict__ Ahg, const unsigned short* __restrict__ Alg,
    const unsigned short* __restrict__ Bhg, const unsigned short* __restrict__ Blg,
    const float* __restrict__ bias, float* __restrict__ C,
    int M, int N, int K)
{
    extern __shared__ unsigned short smg[];
    int t = threadIdx.x;
    int wid = t >> 5, lane = t & 31;
    int wm = wid >> 2, wn = wid & 3;
    int g = lane >> 2, q = lane & 3;
    int mb = blockIdx.y * 128, nb = blockIdx.x * 128;

    float acc[4][4][4];
    #pragma unroll
    for (int mt = 0; mt < 4; ++mt)
        #pragma unroll
        for (int nt = 0; nt < 4; ++nt)
            #pragma unroll
            for (int e = 0; e < 4; ++e) acc[mt][nt][e] = 0.f;

    const int NKB = K >> 5;

    // stage loader: 512 chunks of 16B per tile, 4 tiles, 256 threads -> 8 cp16
    auto load_stage = [&](int st, int k0) {
        unsigned short* base = smg + st * GSTAGE;
        #pragma unroll
        for (int i = 0; i < 2; ++i) {
            int ch = t + i * 256;          // 0..511
            int row = ch >> 2, c = ch & 3; // c*8 bf16 within 32
            int soff = row * GPAD + c * 8;
            size_t goffA = (size_t)(mb + row) * K + k0 + c * 8;
            size_t goffB = (size_t)(nb + row) * K + k0 + c * 8;
            cp16(base + soff,             Ahg + goffA);
            cp16(base + GTILE + soff,     Alg + goffA);
            cp16(base + 2 * GTILE + soff, Bhg + goffB);
            cp16(base + 3 * GTILE + soff, Blg + goffB);
        }
        cp_commit();
    };

    load_stage(0, 0);

    for (int kb = 0; kb < NKB; ++kb) {
        if (kb + 1 < NKB) { load_stage((kb + 1) & 1, (kb + 1) << 5); cp_wait1(); }
        else              { cp_wait0(); }
        __syncthreads();

        unsigned short* base = smg + (kb & 1) * GSTAGE;
        unsigned short* sAh = base;
        unsigned short* sAl = base + GTILE;
        unsigned short* sBh = base + 2 * GTILE;
        unsigned short* sBl = base + 3 * GTILE;

        #pragma unroll
        for (int kk = 0; kk < 2; ++kk) {
            uint32_t ah[4][4], al[4][4];
            #pragma unroll
            for (int mt = 0; mt < 4; ++mt) {
                int r = wm * 64 + mt * 16 + (lane & 15);
                int c = kk * 16 + (lane >> 4) * 8;
                ldsm4(ah[mt], sAh + r * GPAD + c);
                ldsm4(al[mt], sAl + r * GPAD + c);
            }
            uint32_t bh2[4][2], bl2[4][2];
            #pragma unroll
            for (int p = 0; p < 2; ++p) {
                int r = wn * 32 + p * 16 + ((lane >> 4) & 1) * 8 + (lane & 7);
                int c = kk * 16 + ((lane >> 3) & 1) * 8;
                uint32_t tmp[4];
                ldsm4(tmp, sBh + r * GPAD + c);
                bh2[2*p][0] = tmp[0]; bh2[2*p][1] = tmp[1];
                bh2[2*p+1][0] = tmp[2]; bh2[2*p+1][1] = tmp[3];
                ldsm4(tmp, sBl + r * GPAD + c);
                bl2[2*p][0] = tmp[0]; bl2[2*p][1] = tmp[1];
                bl2[2*p+1][0] = tmp[2]; bl2[2*p+1][1] = tmp[3];
            }
            #pragma unroll
            for (int mt = 0; mt < 4; ++mt)
                #pragma unroll
                for (int nt = 0; nt < 4; ++nt) {
                    mma_bf16(acc[mt][nt], ah[mt], bh2[nt]);
                    mma_bf16(acc[mt][nt], ah[mt], bl2[nt]);
                    mma_bf16(acc[mt][nt], al[mt], bh2[nt]);
                }
        }
        __syncthreads();
    }

    #pragma unroll
    for (int mt = 0; mt < 4; ++mt) {
        #pragma unroll
        for (int nt = 0; nt < 4; ++nt) {
            int r = mb + wm * 64 + mt * 16 + g;
            int c = nb + wn * 32 + nt * 8 + q * 2;
            float b0 = bias[c], b1 = bias[c + 1];
            float2 v0; v0.x = acc[mt][nt][0] + b0; v0.y = acc[mt][nt][1] + b1;
            float2 v1; v1.x = acc[mt][nt][2] + b0; v1.y = acc[mt][nt][3] + b1;
            *(float2*)(C + (size_t)r * N + c)       = v0;
            *(float2*)(C + (size_t)(r + 8) * N + c) = v1;
        }
    }
}

// ---------------------------------------------------------------------------
// 3) RoPE + head-major split-bf16 relayout for Q (pre-scaled) and K.
// ---------------------------------------------------------------------------
__global__ void __launch_bounds__(256) rope_convert_kernel(
    const float* __restrict__ qkv,
    unsigned short* __restrict__ Qh, unsigned short* __restrict__ Ql,
    unsigned short* __restrict__ Kh, unsigned short* __restrict__ Kl)
{
    int idx = blockIdx.x * 256 + threadIdx.x;   // B*S*H*32
    int i  = idx & 31;
    int h  = (idx >> 5) & 15;
    int sb = idx >> 9;
    int s  = sb & (S_LEN - 1);
    int b  = sb >> 11;
    const double C = 0.28782844202394213;       // ln(10000)/32
    double ang = (double)s * exp(-C * (double)i);
    double n   = rint(ang * 0.15915494309189535); // 1/(2*pi)
    float ar   = (float)(ang - n * 6.283185307179586);
    float c  = cosf(ar);
    float sn = sinf(ar);

    size_t base = (size_t)sb * QKVD + h * (3 * HDIM);
    float q1 = qkv[base + i],      q2 = qkv[base + 32 + i];
    float k1 = qkv[base + 64 + i], k2 = qkv[base + 96 + i];
    float qo1 = (q1 * c - q2 * sn) * 0.125f;
    float qo2 = (q2 * c + q1 * sn) * 0.125f;
    float ko1 = k1 * c - k2 * sn;
    float ko2 = k2 * c + k1 * sn;

    size_t dst = ((size_t)(b * NHEAD + h) * S_LEN + s) * HDIM;
    float hq1 = __bfloat162float(__float2bfloat16_rn(qo1));
    float hq2 = __bfloat162float(__float2bfloat16_rn(qo2));
    float hk1 = __bfloat162float(__float2bfloat16_rn(ko1));
    float hk2 = __bfloat162float(__float2bfloat16_rn(ko2));
    Qh[dst + i]      = __bfloat16_as_ushort(__float2bfloat16_rn(qo1));
    Qh[dst + 32 + i] = __bfloat16_as_ushort(__float2bfloat16_rn(qo2));
    Ql[dst + i]      = __bfloat16_as_ushort(__float2bfloat16_rn(qo1 - hq1));
    Ql[dst + 32 + i] = __bfloat16_as_ushort(__float2bfloat16_rn(qo2 - hq2));
    Kh[dst + i]      = __bfloat16_as_ushort(__float2bfloat16_rn(ko1));
    Kh[dst + 32 + i] = __bfloat16_as_ushort(__float2bfloat16_rn(ko2));
    Kl[dst + i]      = __bfloat16_as_ushort(__float2bfloat16_rn(ko1 - hk1));
    Kl[dst + 32 + i] = __bfloat16_as_ushort(__float2bfloat16_rn(ko2 - hk2));
}

// ---------------------------------------------------------------------------
// 3b) V transpose + split: Vt[bh][d][s] from qkv v-part, tiled via smem.
// ---------------------------------------------------------------------------
__global__ void __launch_bounds__(256) v_transpose_kernel(
    const float* __restrict__ qkv,
    unsigned short* __restrict__ Vth, unsigned short* __restrict__ Vtl)
{
    __shared__ float tile[64][67];
    int st = blockIdx.x, bh = blockIdx.y;
    int b = bh >> 4, h = bh & 15;
    int t = threadIdx.x;
    #pragma unroll
    for (int it = 0; it < 4; ++it) {
        int id = t + it * 256;            // 0..1023
        int sl = id >> 4, f4 = id & 15;
        int sb = b * S_LEN + st * 64 + sl;
        float4 v = *(const float4*)(qkv + (size_t)sb * QKVD + h * 192 + 128 + f4 * 4);
        tile[sl][f4*4+0] = v.x; tile[sl][f4*4+1] = v.y;
        tile[sl][f4*4+2] = v.z; tile[sl][f4*4+3] = v.w;
    }
    __syncthreads();
    #pragma unroll
    for (int it = 0; it < 16; ++it) {
        int d  = it * 4 + (t >> 6);
        int sl = t & 63;
        float v = tile[sl][d];
        float hv = __bfloat162float(__float2bfloat16_rn(v));
        size_t dst = ((size_t)bh * HDIM + d) * S_LEN + st * 64 + sl;
        Vth[dst] = __bfloat16_as_ushort(__float2bfloat16_rn(v));
        Vtl[dst] = __bfloat16_as_ushort(__float2bfloat16_rn(v - hv));
    }
}

// ---------------------------------------------------------------------------
// 4) Tensor-core flash attention. Block = (qt: 128 q rows, bh). 8 warps,
//    warp owns 16 q rows. Split-bf16 QK^T and PV (3 MMAs each).
//    Smem rows padded to 72 bf16.
// ---------------------------------------------------------------------------
#define APAD 72
#define AQT (128 * APAD)   // Q tile ushorts
#define AKT (64 * APAD)    // K/V tile ushorts
// layout: QH | QL | KH | KL | VH | VL
#define ATT_SMEM ((2 * AQT + 4 * AKT) * 2)

__global__ void __launch_bounds__(256) attn_mma_kernel(
    const unsigned short* __restrict__ Qh, const unsigned short* __restrict__ Ql,
    const unsigned short* __restrict__ Kh, const unsigned short* __restrict__ Kl,
    const unsigned short* __restrict__ Vth, const unsigned short* __restrict__ Vtl,
    unsigned short* __restrict__ Ch, unsigned short* __restrict__ Cl)
{
    extern __shared__ unsigned short sma[];
    unsigned short* sQh = sma;
    unsigned short* sQl = sma + AQT;
    unsigned short* sKh = sma + 2 * AQT;
    unsigned short* sKl = sKh + AKT;
    unsigned short* sVh = sKl + AKT;
    unsigned short* sVl = sVh + AKT;

    int qt = blockIdx.x, bh = blockIdx.y;
    int b = bh >> 4, h = bh & 15;
    int t = threadIdx.x;
    int w = t >> 5, lane = t & 31;
    int g = lane >> 2, q = lane & 3;

    // stage Q (hi+lo)
    size_t qbase = ((size_t)bh * S_LEN + qt * 128) * HDIM;
    #pragma unroll
    for (int i = 0; i < 4; ++i) {
        int ch = t + i * 256;             // 0..1023
        int row = ch >> 3, c = ch & 7;
        cp16(sQh + row * APAD + c * 8, Qh + qbase + row * 64 + c * 8);
        cp16(sQl + row * APAD + c * 8, Ql + qbase + row * 64 + c * 8);
    }
    cp_commit(); cp_wait0();
    __syncthreads();

    // Q fragments (held in registers for whole kernel)
    uint32_t qfh[4][4], qfl[4][4];
    #pragma unroll
    for (int kk = 0; kk < 4; ++kk) {
        int r = w * 16 + (lane & 15);
        int c = kk * 16 + (lane >> 4) * 8;
        ldsm4(qfh[kk], sQh + r * APAD + c);
        ldsm4(qfl[kk], sQl + r * APAD + c);
    }

    float o[8][4];
    #pragma unroll
    for (int nt = 0; nt < 8; ++nt)
        #pragma unroll
        for (int e = 0; e < 4; ++e) o[nt][e] = 0.f;
    float mA = -1e30f, mB = -1e30f, lA = 0.f, lB = 0.f;

    int qrA = qt * 128 + w * 16 + g;      // rows: qrA (e0,e1), qrA+8 (e2,e3)
    int qmax = qt * 128 + w * 16 + 15;
    int nk = 2 * qt + 2;

    for (int kt = 0; kt < nk; ++kt) {
        __syncthreads();   // prior iteration's smem reads complete
        {
            size_t kbase = ((size_t)bh * S_LEN + kt * 64) * HDIM;
            #pragma unroll
            for (int i = 0; i < 2; ++i) {
                int ch = t + i * 256;     // 0..511
                int row = ch >> 3, c = ch & 7;
                int soff = row * APAD + c * 8;
                cp16(sKh + soff, Kh + kbase + row * 64 + c * 8);
                cp16(sKl + soff, Kl + kbase + row * 64 + c * 8);
                size_t vsrc = ((size_t)bh * HDIM + row) * S_LEN + kt * 64 + c * 8;
                cp16(sVh + soff, Vth + vsrc);
                cp16(sVl + soff, Vtl + vsrc);
            }
        }
        cp_commit(); cp_wait0();
        __syncthreads();

        if (kt * 64 > qmax) continue;   // fully masked for this warp

        // S = Q K^T (split x3)
        float s_acc[8][4];
        #pragma unroll
        for (int nt = 0; nt < 8; ++nt)
            #pragma unroll
            for (int e = 0; e < 4; ++e) s_acc[nt][e] = 0.f;

        #pragma unroll
        for (int kk = 0; kk < 4; ++kk) {
            uint32_t bh2[8][2], bl2[8][2];
            #pragma unroll
            for (int p = 0; p < 4; ++p) {
                int r = p * 16 + ((lane >> 4) & 1) * 8 + (lane & 7);
                int c = kk * 16 + ((lane >> 3) & 1) * 8;
                uint32_t tmp[4];
                ldsm4(tmp, sKh + r * APAD + c);
                bh2[2*p][0] = tmp[0]; bh2[2*p][1] = tmp[1];
                bh2[2*p+1][0] = tmp[2]; bh2[2*p+1][1] = tmp[3];
                ldsm4(tmp, sKl + r * APAD + c);
                bl2[2*p][0] = tmp[0]; bl2[2*p][1] = tmp[1];
                bl2[2*p+1][0] = tmp[2]; bl2[2*p+1][1] = tmp[3];
            }
            #pragma unroll
            for (int nt = 0; nt < 8; ++nt) {
                mma_bf16(s_acc[nt], qfh[kk], bh2[nt]);
                mma_bf16(s_acc[nt], qfh[kk], bl2[nt]);
                mma_bf16(s_acc[nt], qfl[kk], bh2[nt]);
            }
        }

        // causal mask
        int kb0 = kt * 64;
        if (kb0 + 63 > qrA) {
            #pragma unroll
            for (int nt = 0; nt < 8; ++nt) {
                int colb = kb0 + nt * 8 + 2 * q;
                if (colb     > qrA)     s_acc[nt][0] = -1e30f;
                if (colb + 1 > qrA)     s_acc[nt][1] = -1e30f;
                if (colb     > qrA + 8) s_acc[nt][2] = -1e30f;
                if (colb + 1 > qrA + 8) s_acc[nt][3] = -1e30f;
            }
        }

        // online softmax (rows A,B per thread; row spread over 4 lanes of quad)
        float mxA = -1e30f, mxB = -1e30f;
        #pragma unroll
        for (int nt = 0; nt < 8; ++nt) {
            mxA = fmaxf(mxA, fmaxf(s_acc[nt][0], s_acc[nt][1]));
            mxB = fmaxf(mxB, fmaxf(s_acc[nt][2], s_acc[nt][3]));
        }
        mxA = fmaxf(mxA, __shfl_xor_sync(0xffffffffu, mxA, 1));
        mxA = fmaxf(mxA, __shfl_xor_sync(0xffffffffu, mxA, 2));
        mxB = fmaxf(mxB, __shfl_xor_sync(0xffffffffu, mxB, 1));
        mxB = fmaxf(mxB, __shfl_xor_sync(0xffffffffu, mxB, 2));
        float mnA = fmaxf(mA, mxA), mnB = fmaxf(mB, mxB);
        float corrA = __expf(mA - mnA), corrB = __expf(mB - mnB);
        float psA = 0.f, psB = 0.f;
        #pragma unroll
        for (int nt = 0; nt < 8; ++nt) {
            s_acc[nt][0] = __expf(s_acc[nt][0] - mnA); psA += s_acc[nt][0];
            s_acc[nt][1] = __expf(s_acc[nt][1] - mnA); psA += s_acc[nt][1];
            s_acc[nt][2] = __expf(s_acc[nt][2] - mnB); psB += s_acc[nt][2];
            s_acc[nt][3] = __expf(s_acc[nt][3] - mnB); psB += s_acc[nt][3];
        }
        psA += __shfl_xor_sync(0xffffffffu, psA, 1);
        psA += __shfl_xor_sync(0xffffffffu, psA, 2);
        psB += __shfl_xor_sync(0xffffffffu, psB, 1);
        psB += __shfl_xor_sync(0xffffffffu, psB, 2);
        lA = lA * corrA + psA;  mA = mnA;
        lB = lB * corrB + psB;  mB = mnB;
        #pragma unroll
        for (int nt = 0; nt < 8; ++nt) {
            o[nt][0] *= corrA; o[nt][1] *= corrA;
            o[nt][2] *= corrB; o[nt][3] *= corrB;
        }

        // O += P V (split x3); P fragments packed per k-chunk from s_acc
        #pragma unroll
        for (int kk = 0; kk < 4; ++kk) {
            int n0 = 2 * kk, n1 = 2 * kk + 1;
            uint32_t ph[4], pl[4];
            ph[0] = f2bf2(s_acc[n0][0], s_acc[n0][1]);
            ph[1] = f2bf2(s_acc[n0][2], s_acc[n0][3]);
            ph[2] = f2bf2(s_acc[n1][0], s_acc[n1][1]);
            ph[3] = f2bf2(s_acc[n1][2], s_acc[n1][3]);
            {
                float r00 = s_acc[n0][0] - __bfloat162float(__float2bfloat16_rn(s_acc[n0][0]));
                float r01 = s_acc[n0][1] - __bfloat162float(__float2bfloat16_rn(s_acc[n0][1]));
                float r02 = s_acc[n0][2] - __bfloat162float(__float2bfloat16_rn(s_acc[n0][2]));
                float r03 = s_acc[n0][3] - __bfloat162float(__float2bfloat16_rn(s_acc[n0][3]));
                float r10 = s_acc[n1][0] - __bfloat162float(__float2bfloat16_rn(s_acc[n1][0]));
                float r11 = s_acc[n1][1] - __bfloat162float(__float2bfloat16_rn(s_acc[n1][1]));
                float r12 = s_acc[n1][2] - __bfloat162float(__float2bfloat16_rn(s_acc[n1][2]));
                float r13 = s_acc[n1][3] - __bfloat162float(__float2bfloat16_rn(s_acc[n1][3]));
                pl[0] = f2bf2(r00, r01); pl[1] = f2bf2(r02, r03);
                pl[2] = f2bf2(r10, r11); pl[3] = f2bf2(r12, r13);
            }
            uint32_t vh2[8][2], vl2[8][2];
            #pragma unroll
            for (int p = 0; p < 4; ++p) {
                int r = p * 16 + ((lane >> 4) & 1) * 8 + (lane & 7);
                int c = kk * 16 + ((lane >> 3) & 1) * 8;
                uint32_t tmp[4];
                ldsm4(tmp, sVh + r * APAD + c);
                vh2[2*p][0] = tmp[0]; vh2[2*p][1] = tmp[1];
                vh2[2*p+1][0] = tmp[2]; vh2[2*p+1][1] = tmp[3];
                ldsm4(tmp, sVl + r * APAD + c);
                vl2[2*p][0] = tmp[0]; vl2[2*p][1] = tmp[1];
                vl2[2*p+1][0] = tmp[2]; vl2[2*p+1][1] = tmp[3];
            }
            #pragma unroll
            for (int nt = 0; nt < 8; ++nt) {
                mma_bf16(o[nt], ph, vh2[nt]);
                mma_bf16(o[nt], ph, vl2[nt]);
                mma_bf16(o[nt], pl, vh2[nt]);
            }
        }
    }

    // epilogue: normalize, split-bf16 write to ctx hi/lo
    float invA = 1.f / lA, invB = 1.f / lB;
    int rowA = qt * 128 + w * 16 + g;
    size_t baseA = ((size_t)(b * S_LEN + rowA)) * DMODEL + h * HDIM;
    size_t baseB = baseA + (size_t)8 * DMODEL;
    #pragma unroll
    for (int nt = 0; nt < 8; ++nt) {
        int c = nt * 8 + 2 * q;
        float a0 = o[nt][0] * invA, a1 = o[nt][1] * invA;
        float b0 = o[nt][2] * invB, b1 = o[nt][3] * invB;
        float ha0 = __bfloat162float(__float2bfloat16_rn(a0));
        float ha1 = __bfloat162float(__float2bfloat16_rn(a1));
        float hb0 = __bfloat162float(__float2bfloat16_rn(b0));
        float hb1 = __bfloat162float(__float2bfloat16_rn(b1));
        *(uint32_t*)(Ch + baseA + c) = f2bf2(ha0, ha1);
        *(uint32_t*)(Cl + baseA + c) = f2bf2(a0 - ha0, a1 - ha1);
        *(uint32_t*)(Ch + baseB + c) = f2bf2(hb0, hb1);
        *(uint32_t*)(Cl + baseB + c) = f2bf2(b0 - hb0, b1 - hb1);
    }
}

// ---------------------------------------------------------------------------
// Launcher
// ---------------------------------------------------------------------------
extern "C" void kernel_launch(void* const* d_in, const int* in_sizes, int n_in,
                              void* d_out, int out_size)
{
    const float* hs     = (const float*)d_in[0];
    const float* gamma  = (const float*)d_in[1];
    const float* beta   = (const float*)d_in[2];
    const float* qkv_w  = (const float*)d_in[3];
    const float* qkv_b  = (const float*)d_in[4];
    const float* proj_w = (const float*)d_in[5];
    const float* proj_b = (const float*)d_in[6];
    float* out = (float*)d_out;

    void *pqkv, *pxh, *pxl, *pwqh, *pwql, *pwph, *pwpl, *pch, *pcl;
    void *pqh, *pql, *pkh, *pkl, *pvh, *pvl;
    cudaGetSymbolAddress(&pqkv, g_qkv);
    cudaGetSymbolAddress(&pxh,  g_xh);  cudaGetSymbolAddress(&pxl,  g_xl);
    cudaGetSymbolAddress(&pwqh, g_wqh); cudaGetSymbolAddress(&pwql, g_wql);
    cudaGetSymbolAddress(&pwph, g_wph); cudaGetSymbolAddress(&pwpl, g_wpl);
    cudaGetSymbolAddress(&pch,  g_ch);  cudaGetSymbolAddress(&pcl,  g_cl);
    cudaGetSymbolAddress(&pqh,  g_qhh); cudaGetSymbolAddress(&pql,  g_qll);
    cudaGetSymbolAddress(&pkh,  g_khh); cudaGetSymbolAddress(&pkl,  g_kll);
    cudaGetSymbolAddress(&pvh,  g_vth); cudaGetSymbolAddress(&pvl,  g_vtl);

    cudaFuncSetAttribute(mma_gemm_smem,
        cudaFuncAttributeMaxDynamicSharedMemorySize, GEMM_SMEM);
    cudaFuncSetAttribute(attn_mma_kernel,
        cudaFuncAttributeMaxDynamicSharedMemorySize, ATT_SMEM);

    // 1) LayerNorm + split
    ln_split_kernel<<<ROWS, 256>>>(hs, gamma, beta,
        (unsigned short*)pxh, (unsigned short*)pxl);

    // weight splits
    split_bf16_kernel<<<(QKVD*DMODEL/4)/256, 256>>>(qkv_w,
        (unsigned short*)pwqh, (unsigned short*)pwql, QKVD*DMODEL/4);
    split_bf16_kernel<<<(DMODEL*DMODEL/4)/256, 256>>>(proj_w,
        (unsigned short*)pwph, (unsigned short*)pwpl, DMODEL*DMODEL/4);

    // 2) QKV GEMM
    mma_gemm_smem<<<dim3(QKVD/128, ROWS/128), 256, GEMM_SMEM>>>(
        (unsigned short*)pxh, (unsigned short*)pxl,
        (unsigned short*)pwqh, (unsigned short*)pwql,
        qkv_b, (float*)pqkv, ROWS, QKVD, DMODEL);

    // 3) RoPE + relayout, V transpose
    rope_convert_kernel<<<(BATCH*S_LEN*NHEAD*32)/256, 256>>>((float*)pqkv,
        (unsigned short*)pqh, (unsigned short*)pql,
        (unsigned short*)pkh, (unsigned short*)pkl);
    v_transpose_kernel<<<dim3(S_LEN/64, BH), 256>>>((float*)pqkv,
        (unsigned short*)pvh, (unsigned short*)pvl);

    // 4) Attention (writes split-bf16 ctx)
    attn_mma_kernel<<<dim3(S_LEN/128, BH), 256, ATT_SMEM>>>(
        (unsigned short*)pqh, (unsigned short*)pql,
        (unsigned short*)pkh, (unsigned short*)pkl,
        (unsigned short*)pvh, (unsigned short*)pvl,
        (unsigned short*)pch, (unsigned short*)pcl);

    // 5) Output projection
    mma_gemm_smem<<<dim3(DMODEL/128, ROWS/128), 256, GEMM_SMEM>>>(
        (unsigned short*)pch, (unsigned short*)pcl,
        (unsigned short*)pwph, (unsigned short*)pwpl,
        proj_b, out, ROWS, DMODEL, DMODEL);
}

// round 5
// speedup vs baseline: 5.2413x; 1.0250x over previous
#include <cuda_runtime.h>
#include <cuda_bf16.h>
#include <math.h>
#include <stdint.h>

// Problem constants
#define BATCH   2
#define S_LEN   2048
#define DMODEL  1024
#define NHEAD   16
#define HDIM    64
#define QKVD    (3*DMODEL)     // 3072
#define ROWS    (BATCH*S_LEN)  // 4096
#define BH      (BATCH*NHEAD)  // 32

// Scratch (device globals: allocation-free per harness rules)
__device__ float g_qkv[ROWS * QKVD];                       // qkv fp32 (pre-rope)
__device__ unsigned short g_xh[ROWS * DMODEL],   g_xl[ROWS * DMODEL];
__device__ unsigned short g_wqh[QKVD * DMODEL],  g_wql[QKVD * DMODEL];
__device__ unsigned short g_wph[DMODEL * DMODEL],g_wpl[DMODEL * DMODEL];
__device__ unsigned short g_ch[ROWS * DMODEL],   g_cl[ROWS * DMODEL];
// head-major bf16 split q/k (post-rope) and transposed v
__device__ unsigned short g_qhh[BH * S_LEN * HDIM], g_qll[BH * S_LEN * HDIM];
__device__ unsigned short g_khh[BH * S_LEN * HDIM], g_kll[BH * S_LEN * HDIM];
__device__ unsigned short g_vth[BH * HDIM * S_LEN], g_vtl[BH * HDIM * S_LEN];

// ---------------------------------------------------------------------------
// helpers
// ---------------------------------------------------------------------------
__device__ __forceinline__ uint32_t f2bf2(float lo, float hi) {
    __nv_bfloat162 t = __floats2bfloat162_rn(lo, hi);
    return *reinterpret_cast<uint32_t*>(&t);
}
__device__ __forceinline__ uint32_t sptr(const void* p) {
    return (uint32_t)__cvta_generic_to_shared(p);
}
__device__ __forceinline__ void cp16(void* dst, const void* src) {
    asm volatile("cp.async.cg.shared.global [%0], [%1], 16;\n"
                 :: "r"(sptr(dst)), "l"(src));
}
__device__ __forceinline__ void cp_commit() { asm volatile("cp.async.commit_group;\n"); }
__device__ __forceinline__ void cp_wait0()  { asm volatile("cp.async.wait_group 0;\n"); }
__device__ __forceinline__ void cp_wait1()  { asm volatile("cp.async.wait_group 1;\n"); }

__device__ __forceinline__ void ldsm4(uint32_t* r, const void* p) {
    asm volatile("ldmatrix.sync.aligned.m8n8.x4.shared.b16 {%0,%1,%2,%3}, [%4];\n"
                 : "=r"(r[0]), "=r"(r[1]), "=r"(r[2]), "=r"(r[3]) : "r"(sptr(p)));
}
__device__ __forceinline__ void mma_bf16(float* c, const uint32_t* a, const uint32_t* b) {
    asm volatile(
        "mma.sync.aligned.m16n8k16.row.col.f32.bf16.bf16.f32 "
        "{%0,%1,%2,%3}, {%4,%5,%6,%7}, {%8,%9}, {%0,%1,%2,%3};\n"
        : "+f"(c[0]), "+f"(c[1]), "+f"(c[2]), "+f"(c[3])
        : "r"(a[0]), "r"(a[1]), "r"(a[2]), "r"(a[3]), "r"(b[0]), "r"(b[1]));
}

// ---------------------------------------------------------------------------
// 1) LayerNorm fused with split-bf16 output
// ---------------------------------------------------------------------------
__global__ void __launch_bounds__(256) ln_split_kernel(
    const float* __restrict__ x, const float* __restrict__ gamma,
    const float* __restrict__ beta, unsigned short* __restrict__ yh,
    unsigned short* __restrict__ yl)
{
    __shared__ float red_s[8], red_ss[8];
    __shared__ float sh_mean, sh_inv;
    int row = blockIdx.x;
    int tid = threadIdx.x;
    const float4* xr = (const float4*)(x + (size_t)row * DMODEL);
    float4 v = xr[tid];
    float s  = v.x + v.y + v.z + v.w;
    float ss = v.x*v.x + v.y*v.y + v.z*v.z + v.w*v.w;
    #pragma unroll
    for (int off = 16; off > 0; off >>= 1) {
        s  += __shfl_down_sync(0xffffffffu, s,  off);
        ss += __shfl_down_sync(0xffffffffu, ss, off);
    }
    int wid = tid >> 5, lane = tid & 31;
    if (lane == 0) { red_s[wid] = s; red_ss[wid] = ss; }
    __syncthreads();
    if (tid == 0) {
        float S = 0.f, SS = 0.f;
        #pragma unroll
        for (int i = 0; i < 8; ++i) { S += red_s[i]; SS += red_ss[i]; }
        float mean = S * (1.f / DMODEL);
        float var  = SS * (1.f / DMODEL) - mean * mean;
        sh_mean = mean;
        sh_inv  = rsqrtf(var + 1e-5f);
    }
    __syncthreads();
    float mean = sh_mean, inv = sh_inv;
    float4 gv = ((const float4*)gamma)[tid];
    float4 bv = ((const float4*)beta)[tid];
    float o0 = (v.x - mean) * inv * gv.x + bv.x;
    float o1 = (v.y - mean) * inv * gv.y + bv.y;
    float o2 = (v.z - mean) * inv * gv.z + bv.z;
    float o3 = (v.w - mean) * inv * gv.w + bv.w;
    float h0 = __bfloat162float(__float2bfloat16_rn(o0));
    float h1 = __bfloat162float(__float2bfloat16_rn(o1));
    float h2 = __bfloat162float(__float2bfloat16_rn(o2));
    float h3 = __bfloat162float(__float2bfloat16_rn(o3));
    uint2 hv = make_uint2(f2bf2(h0, h1), f2bf2(h2, h3));
    uint2 lv = make_uint2(f2bf2(o0 - h0, o1 - h1), f2bf2(o2 - h2, o3 - h3));
    *(uint2*)(yh + (size_t)row * DMODEL + tid * 4) = hv;
    *(uint2*)(yl + (size_t)row * DMODEL + tid * 4) = lv;
}

// ---------------------------------------------------------------------------
// split fp32 -> (hi, lo) bf16, 4 elements/thread (weights)
// ---------------------------------------------------------------------------
__global__ void __launch_bounds__(256) split_bf16_kernel(
    const float* __restrict__ x, unsigned short* __restrict__ hi,
    unsigned short* __restrict__ lo, int n4)
{
    int i = blockIdx.x * 256 + threadIdx.x;
    if (i >= n4) return;
    float4 v = ((const float4*)x)[i];
    float h0 = __bfloat162float(__float2bfloat16_rn(v.x));
    float h1 = __bfloat162float(__float2bfloat16_rn(v.y));
    float h2 = __bfloat162float(__float2bfloat16_rn(v.z));
    float h3 = __bfloat162float(__float2bfloat16_rn(v.w));
    uint2 hv = make_uint2(f2bf2(h0, h1), f2bf2(h2, h3));
    uint2 lv = make_uint2(f2bf2(v.x - h0, v.y - h1), f2bf2(v.z - h2, v.w - h3));
    *(uint2*)(hi + (size_t)i * 4) = hv;
    *(uint2*)(lo + (size_t)i * 4) = lv;
}

// ---------------------------------------------------------------------------
// 2) Smem-staged double-buffered split-bf16 MMA GEMM.
//    C[M,N] = A[M,K] @ B[N,K]^T + bias.
//    Block 128x128, BK=32, 4 warps (2x2), warp tile 64x64.
//    Smem rows padded to 40 bf16 -> conflict-free LDSM/cp.async.
// ---------------------------------------------------------------------------
#define GPAD 40
#define GTILE (128 * GPAD)            // ushorts per tile
#define GSTAGE (4 * GTILE)            // Ah,Al,Bh,Bl
#define GEMM_SMEM (2 * GSTAGE * 2)    // bytes = 163840/2 = 81920? (2 stages)

__global__ void __launch_bounds__(128) mma_gemm_smem(
    const unsigned short* __restrict__ Ahg, const unsigned short* __restrict__ Alg,
    const unsigned short* __restrict__ Bhg, const unsigned short* __restrict__ Blg,
    const float* __restrict__ bias, float* __restrict__ C,
    int M, int N, int K)
{
    extern __shared__ unsigned short smg[];
    int t = threadIdx.x;
    int wid = t >> 5, lane = t & 31;
    int wm = wid >> 1, wn = wid & 1;
    int g = lane >> 2, q = lane & 3;
    int mb = blockIdx.y * 128, nb = blockIdx.x * 128;

    float acc[4][8][4];
    #pragma unroll
    for (int mt = 0; mt < 4; ++mt)
        #pragma unroll
        for (int nt = 0; nt < 8; ++nt)
            #pragma unroll
            for (int e = 0; e < 4; ++e) acc[mt][nt][e] = 0.f;

    const int NKB = K >> 5;

    // stage loader: 512 chunks of 16B per tile, 4 tiles, 128 threads -> 16 cp16
    auto load_stage = [&](int st, int k0) {
        unsigned short* base = smg + st * GSTAGE;
        #pragma unroll
        for (int i = 0; i < 4; ++i) {
            int ch = t + i * 128;          // 0..511
            int row = ch >> 2, c = ch & 3; // c*8 bf16 within 32
            int soff = row * GPAD + c * 8;
            size_t goffA = (size_t)(mb + row) * K + k0 + c * 8;
            size_t goffB = (size_t)(nb + row) * K + k0 + c * 8;
            cp16(base + soff,             Ahg + goffA);
            cp16(base + GTILE + soff,     Alg + goffA);
            cp16(base + 2 * GTILE + soff, Bhg + goffB);
            cp16(base + 3 * GTILE + soff, Blg + goffB);
        }
        cp_commit();
    };

    load_stage(0, 0);

    for (int kb = 0; kb < NKB; ++kb) {
        if (kb + 1 < NKB) { load_stage((kb + 1) & 1, (kb + 1) << 5); cp_wait1(); }
        else              { cp_wait0(); }
        __syncthreads();

        unsigned short* base = smg + (kb & 1) * GSTAGE;
        unsigned short* sAh = base;
        unsigned short* sAl = base + GTILE;
        unsigned short* sBh = base + 2 * GTILE;
        unsigned short* sBl = base + 3 * GTILE;

        #pragma unroll
        for (int kk = 0; kk < 2; ++kk) {
            uint32_t ah[4][4], al[4][4];
            #pragma unroll
            for (int mt = 0; mt < 4; ++mt) {
                int r = wm * 64 + mt * 16 + (lane & 15);
                int c = kk * 16 + (lane >> 4) * 8;
                ldsm4(ah[mt], sAh + r * GPAD + c);
                ldsm4(al[mt], sAl + r * GPAD + c);
            }
            uint32_t bh2[8][2], bl2[8][2];
            #pragma unroll
            for (int p = 0; p < 4; ++p) {
                int r = wn * 64 + p * 16 + ((lane >> 4) & 1) * 8 + (lane & 7);
                int c = kk * 16 + ((lane >> 3) & 1) * 8;
                uint32_t tmp[4];
                ldsm4(tmp, sBh + r * GPAD + c);
                bh2[2*p][0] = tmp[0]; bh2[2*p][1] = tmp[1];
                bh2[2*p+1][0] = tmp[2]; bh2[2*p+1][1] = tmp[3];
                ldsm4(tmp, sBl + r * GPAD + c);
                bl2[2*p][0] = tmp[0]; bl2[2*p][1] = tmp[1];
                bl2[2*p+1][0] = tmp[2]; bl2[2*p+1][1] = tmp[3];
            }
            #pragma unroll
            for (int mt = 0; mt < 4; ++mt)
                #pragma unroll
                for (int nt = 0; nt < 8; ++nt) {
                    mma_bf16(acc[mt][nt], ah[mt], bh2[nt]);
                    mma_bf16(acc[mt][nt], ah[mt], bl2[nt]);
                    mma_bf16(acc[mt][nt], al[mt], bh2[nt]);
                }
        }
        __syncthreads();
    }

    #pragma unroll
    for (int mt = 0; mt < 4; ++mt) {
        #pragma unroll
        for (int nt = 0; nt < 8; ++nt) {
            int r = mb + wm * 64 + mt * 16 + g;
            int c = nb + wn * 64 + nt * 8 + q * 2;
            float b0 = bias[c], b1 = bias[c + 1];
            float2 v0; v0.x = acc[mt][nt][0] + b0; v0.y = acc[mt][nt][1] + b1;
            float2 v1; v1.x = acc[mt][nt][2] + b0; v1.y = acc[mt][nt][3] + b1;
            *(float2*)(C + (size_t)r * N + c)       = v0;
            *(float2*)(C + (size_t)(r + 8) * N + c) = v1;
        }
    }
}

// ---------------------------------------------------------------------------
// 3) RoPE + head-major split-bf16 relayout for Q (pre-scaled) and K.
// ---------------------------------------------------------------------------
__global__ void __launch_bounds__(256) rope_convert_kernel(
    const float* __restrict__ qkv,
    unsigned short* __restrict__ Qh, unsigned short* __restrict__ Ql,
    unsigned short* __restrict__ Kh, unsigned short* __restrict__ Kl)
{
    int idx = blockIdx.x * 256 + threadIdx.x;   // B*S*H*32
    int i  = idx & 31;
    int h  = (idx >> 5) & 15;
    int sb = idx >> 9;
    int s  = sb & (S_LEN - 1);
    int b  = sb >> 11;
    const double C = 0.28782844202394213;       // ln(10000)/32
    double ang = (double)s * exp(-C * (double)i);
    double n   = rint(ang * 0.15915494309189535); // 1/(2*pi)
    float ar   = (float)(ang - n * 6.283185307179586);
    float c  = cosf(ar);
    float sn = sinf(ar);

    size_t base = (size_t)sb * QKVD + h * (3 * HDIM);
    float q1 = qkv[base + i],      q2 = qkv[base + 32 + i];
    float k1 = qkv[base + 64 + i], k2 = qkv[base + 96 + i];
    float qo1 = (q1 * c - q2 * sn) * 0.125f;
    float qo2 = (q2 * c + q1 * sn) * 0.125f;
    float ko1 = k1 * c - k2 * sn;
    float ko2 = k2 * c + k1 * sn;

    size_t dst = ((size_t)(b * NHEAD + h) * S_LEN + s) * HDIM;
    float hq1 = __bfloat162float(__float2bfloat16_rn(qo1));
    float hq2 = __bfloat162float(__float2bfloat16_rn(qo2));
    float hk1 = __bfloat162float(__float2bfloat16_rn(ko1));
    float hk2 = __bfloat162float(__float2bfloat16_rn(ko2));
    Qh[dst + i]      = __bfloat16_as_ushort(__float2bfloat16_rn(qo1));
    Qh[dst + 32 + i] = __bfloat16_as_ushort(__float2bfloat16_rn(qo2));
    Ql[dst + i]      = __bfloat16_as_ushort(__float2bfloat16_rn(qo1 - hq1));
    Ql[dst + 32 + i] = __bfloat16_as_ushort(__float2bfloat16_rn(qo2 - hq2));
    Kh[dst + i]      = __bfloat16_as_ushort(__float2bfloat16_rn(ko1));
    Kh[dst + 32 + i] = __bfloat16_as_ushort(__float2bfloat16_rn(ko2));
    Kl[dst + i]      = __bfloat16_as_ushort(__float2bfloat16_rn(ko1 - hk1));
    Kl[dst + 32 + i] = __bfloat16_as_ushort(__float2bfloat16_rn(ko2 - hk2));
}

// ---------------------------------------------------------------------------
// 3b) V transpose + split: Vt[bh][d][s] from qkv v-part, tiled via smem.
// ---------------------------------------------------------------------------
__global__ void __launch_bounds__(256) v_transpose_kernel(
    const float* __restrict__ qkv,
    unsigned short* __restrict__ Vth, unsigned short* __restrict__ Vtl)
{
    __shared__ float tile[64][67];
    int st = blockIdx.x, bh = blockIdx.y;
    int b = bh >> 4, h = bh & 15;
    int t = threadIdx.x;
    #pragma unroll
    for (int it = 0; it < 4; ++it) {
        int id = t + it * 256;            // 0..1023
        int sl = id >> 4, f4 = id & 15;
        int sb = b * S_LEN + st * 64 + sl;
        float4 v = *(const float4*)(qkv + (size_t)sb * QKVD + h * 192 + 128 + f4 * 4);
        tile[sl][f4*4+0] = v.x; tile[sl][f4*4+1] = v.y;
        tile[sl][f4*4+2] = v.z; tile[sl][f4*4+3] = v.w;
    }
    __syncthreads();
    #pragma unroll
    for (int it = 0; it < 16; ++it) {
        int d  = it * 4 + (t >> 6);
        int sl = t & 63;
        float v = tile[sl][d];
        float hv = __bfloat162float(__float2bfloat16_rn(v));
        size_t dst = ((size_t)bh * HDIM + d) * S_LEN + st * 64 + sl;
        Vth[dst] = __bfloat16_as_ushort(__float2bfloat16_rn(v));
        Vtl[dst] = __bfloat16_as_ushort(__float2bfloat16_rn(v - hv));
    }
}

// ---------------------------------------------------------------------------
// 4) Tensor-core flash attention with double-buffered (prefetched) K/V.
//    Block = (qt: 128 q rows, bh). 8 warps, warp owns 16 q rows.
// ---------------------------------------------------------------------------
#define APAD 72
#define AQT (128 * APAD)   // Q tile ushorts
#define AKT (64 * APAD)    // K/V tile ushorts
#define AST (4 * AKT)      // one K/V stage: Kh,Kl,Vh,Vl
#define ATT_SMEM ((2 * AQT + 2 * AST) * 2)

__global__ void __launch_bounds__(256) attn_mma_kernel(
    const unsigned short* __restrict__ Qh, const unsigned short* __restrict__ Ql,
    const unsigned short* __restrict__ Kh, const unsigned short* __restrict__ Kl,
    const unsigned short* __restrict__ Vth, const unsigned short* __restrict__ Vtl,
    unsigned short* __restrict__ Ch, unsigned short* __restrict__ Cl)
{
    extern __shared__ unsigned short sma[];
    unsigned short* sQh = sma;
    unsigned short* sQl = sma + AQT;
    unsigned short* sKV = sma + 2 * AQT;   // 2 stages of [Kh|Kl|Vh|Vl]

    int qt = blockIdx.x, bh = blockIdx.y;
    int b = bh >> 4, h = bh & 15;
    int t = threadIdx.x;
    int w = t >> 5, lane = t & 31;
    int g = lane >> 2, q = lane & 3;

    auto load_kv = [&](int st, int kt) {
        unsigned short* sg = sKV + st * AST;
        size_t kbase = ((size_t)bh * S_LEN + kt * 64) * HDIM;
        #pragma unroll
        for (int i = 0; i < 2; ++i) {
            int ch = t + i * 256;     // 0..511
            int row = ch >> 3, c = ch & 7;
            int soff = row * APAD + c * 8;
            cp16(sg + soff,           Kh + kbase + row * 64 + c * 8);
            cp16(sg + AKT + soff,     Kl + kbase + row * 64 + c * 8);
            size_t vsrc = ((size_t)bh * HDIM + row) * S_LEN + kt * 64 + c * 8;
            cp16(sg + 2 * AKT + soff, Vth + vsrc);
            cp16(sg + 3 * AKT + soff, Vtl + vsrc);
        }
        cp_commit();
    };

    // stage Q (hi+lo), then prefetch kt=0
    size_t qbase = ((size_t)bh * S_LEN + qt * 128) * HDIM;
    #pragma unroll
    for (int i = 0; i < 4; ++i) {
        int ch = t + i * 256;             // 0..1023
        int row = ch >> 3, c = ch & 7;
        cp16(sQh + row * APAD + c * 8, Qh + qbase + row * 64 + c * 8);
        cp16(sQl + row * APAD + c * 8, Ql + qbase + row * 64 + c * 8);
    }
    cp_commit();
    load_kv(0, 0);
    cp_wait1();          // Q group arrived (kv0 may still be in flight)
    __syncthreads();

    uint32_t qfh[4][4], qfl[4][4];
    #pragma unroll
    for (int kk = 0; kk < 4; ++kk) {
        int r = w * 16 + (lane & 15);
        int c = kk * 16 + (lane >> 4) * 8;
        ldsm4(qfh[kk], sQh + r * APAD + c);
        ldsm4(qfl[kk], sQl + r * APAD + c);
    }

    float o[8][4];
    #pragma unroll
    for (int nt = 0; nt < 8; ++nt)
        #pragma unroll
        for (int e = 0; e < 4; ++e) o[nt][e] = 0.f;
    float mA = -1e30f, mB = -1e30f, lA = 0.f, lB = 0.f;

    int qrA = qt * 128 + w * 16 + g;
    int qmax = qt * 128 + w * 16 + 15;
    int nk = 2 * qt + 2;

    for (int kt = 0; kt < nk; ++kt) {
        // prefetch next tile; stage (kt+1)&1 was last read at iter kt-1,
        // fenced by that iteration's bottom __syncthreads.
        if (kt + 1 < nk) { load_kv((kt + 1) & 1, kt + 1); cp_wait1(); }
        else             { cp_wait0(); }
        __syncthreads();   // stage kt&1 visible to all warps

        if (kt * 64 <= qmax) {
            unsigned short* sg  = sKV + (kt & 1) * AST;
            unsigned short* sKh_ = sg;
            unsigned short* sKl_ = sg + AKT;
            unsigned short* sVh_ = sg + 2 * AKT;
            unsigned short* sVl_ = sg + 3 * AKT;

            float s_acc[8][4];
            #pragma unroll
            for (int nt = 0; nt < 8; ++nt)
                #pragma unroll
                for (int e = 0; e < 4; ++e) s_acc[nt][e] = 0.f;

            #pragma unroll
            for (int kk = 0; kk < 4; ++kk) {
                uint32_t bh2[8][2], bl2[8][2];
                #pragma unroll
                for (int p = 0; p < 4; ++p) {
                    int r = p * 16 + ((lane >> 4) & 1) * 8 + (lane & 7);
                    int c = kk * 16 + ((lane >> 3) & 1) * 8;
                    uint32_t tmp[4];
                    ldsm4(tmp, sKh_ + r * APAD + c);
                    bh2[2*p][0] = tmp[0]; bh2[2*p][1] = tmp[1];
                    bh2[2*p+1][0] = tmp[2]; bh2[2*p+1][1] = tmp[3];
                    ldsm4(tmp, sKl_ + r * APAD + c);
                    bl2[2*p][0] = tmp[0]; bl2[2*p][1] = tmp[1];
                    bl2[2*p+1][0] = tmp[2]; bl2[2*p+1][1] = tmp[3];
                }
                #pragma unroll
                for (int nt = 0; nt < 8; ++nt) {
                    mma_bf16(s_acc[nt], qfh[kk], bh2[nt]);
                    mma_bf16(s_acc[nt], qfh[kk], bl2[nt]);
                    mma_bf16(s_acc[nt], qfl[kk], bh2[nt]);
                }
            }

            int kb0 = kt * 64;
            if (kb0 + 63 > qrA) {
                #pragma unroll
                for (int nt = 0; nt < 8; ++nt) {
                    int colb = kb0 + nt * 8 + 2 * q;
                    if (colb     > qrA)     s_acc[nt][0] = -1e30f;
                    if (colb + 1 > qrA)     s_acc[nt][1] = -1e30f;
                    if (colb     > qrA + 8) s_acc[nt][2] = -1e30f;
                    if (colb + 1 > qrA + 8) s_acc[nt][3] = -1e30f;
                }
            }

            float mxA = -1e30f, mxB = -1e30f;
            #pragma unroll
            for (int nt = 0; nt < 8; ++nt) {
                mxA = fmaxf(mxA, fmaxf(s_acc[nt][0], s_acc[nt][1]));
                mxB = fmaxf(mxB, fmaxf(s_acc[nt][2], s_acc[nt][3]));
            }
            mxA = fmaxf(mxA, __shfl_xor_sync(0xffffffffu, mxA, 1));
            mxA = fmaxf(mxA, __shfl_xor_sync(0xffffffffu, mxA, 2));
            mxB = fmaxf(mxB, __shfl_xor_sync(0xffffffffu, mxB, 1));
            mxB = fmaxf(mxB, __shfl_xor_sync(0xffffffffu, mxB, 2));
            float mnA = fmaxf(mA, mxA), mnB = fmaxf(mB, mxB);
            float corrA = __expf(mA - mnA), corrB = __expf(mB - mnB);
            float psA = 0.f, psB = 0.f;
            #pragma unroll
            for (int nt = 0; nt < 8; ++nt) {
                s_acc[nt][0] = __expf(s_acc[nt][0] - mnA); psA += s_acc[nt][0];
                s_acc[nt][1] = __expf(s_acc[nt][1] - mnA); psA += s_acc[nt][1];
                s_acc[nt][2] = __expf(s_acc[nt][2] - mnB); psB += s_acc[nt][2];
                s_acc[nt][3] = __expf(s_acc[nt][3] - mnB); psB += s_acc[nt][3];
            }
            psA += __shfl_xor_sync(0xffffffffu, psA, 1);
            psA += __shfl_xor_sync(0xffffffffu, psA, 2);
            psB += __shfl_xor_sync(0xffffffffu, psB, 1);
            psB += __shfl_xor_sync(0xffffffffu, psB, 2);
            lA = lA * corrA + psA;  mA = mnA;
            lB = lB * corrB + psB;  mB = mnB;
            #pragma unroll
            for (int nt = 0; nt < 8; ++nt) {
                o[nt][0] *= corrA; o[nt][1] *= corrA;
                o[nt][2] *= corrB; o[nt][3] *= corrB;
            }

            #pragma unroll
            for (int kk = 0; kk < 4; ++kk) {
                int n0 = 2 * kk, n1 = 2 * kk + 1;
                uint32_t ph[4], pl[4];
                ph[0] = f2bf2(s_acc[n0][0], s_acc[n0][1]);
                ph[1] = f2bf2(s_acc[n0][2], s_acc[n0][3]);
                ph[2] = f2bf2(s_acc[n1][0], s_acc[n1][1]);
                ph[3] = f2bf2(s_acc[n1][2], s_acc[n1][3]);
                {
                    float r00 = s_acc[n0][0] - __bfloat162float(__float2bfloat16_rn(s_acc[n0][0]));
                    float r01 = s_acc[n0][1] - __bfloat162float(__float2bfloat16_rn(s_acc[n0][1]));
                    float r02 = s_acc[n0][2] - __bfloat162float(__float2bfloat16_rn(s_acc[n0][2]));
                    float r03 = s_acc[n0][3] - __bfloat162float(__float2bfloat16_rn(s_acc[n0][3]));
                    float r10 = s_acc[n1][0] - __bfloat162float(__float2bfloat16_rn(s_acc[n1][0]));
                    float r11 = s_acc[n1][1] - __bfloat162float(__float2bfloat16_rn(s_acc[n1][1]));
                    float r12 = s_acc[n1][2] - __bfloat162float(__float2bfloat16_rn(s_acc[n1][2]));
                    float r13 = s_acc[n1][3] - __bfloat162float(__float2bfloat16_rn(s_acc[n1][3]));
                    pl[0] = f2bf2(r00, r01); pl[1] = f2bf2(r02, r03);
                    pl[2] = f2bf2(r10, r11); pl[3] = f2bf2(r12, r13);
                }
                uint32_t vh2[8][2], vl2[8][2];
                #pragma unroll
                for (int p = 0; p < 4; ++p) {
                    int r = p * 16 + ((lane >> 4) & 1) * 8 + (lane & 7);
                    int c = kk * 16 + ((lane >> 3) & 1) * 8;
                    uint32_t tmp[4];
                    ldsm4(tmp, sVh_ + r * APAD + c);
                    vh2[2*p][0] = tmp[0]; vh2[2*p][1] = tmp[1];
                    vh2[2*p+1][0] = tmp[2]; vh2[2*p+1][1] = tmp[3];
                    ldsm4(tmp, sVl_ + r * APAD + c);
                    vl2[2*p][0] = tmp[0]; vl2[2*p][1] = tmp[1];
                    vl2[2*p+1][0] = tmp[2]; vl2[2*p+1][1] = tmp[3];
                }
                #pragma unroll
                for (int nt = 0; nt < 8; ++nt) {
                    mma_bf16(o[nt], ph, vh2[nt]);
                    mma_bf16(o[nt], ph, vl2[nt]);
                    mma_bf16(o[nt], pl, vh2[nt]);
                }
            }
        }
        __syncthreads();   // all reads of stage kt&1 done before it is reloaded
    }

    float invA = 1.f / lA, invB = 1.f / lB;
    int rowA = qt * 128 + w * 16 + g;
    size_t baseA = ((size_t)(b * S_LEN + rowA)) * DMODEL + h * HDIM;
    size_t baseB = baseA + (size_t)8 * DMODEL;
    #pragma unroll
    for (int nt = 0; nt < 8; ++nt) {
        int c = nt * 8 + 2 * q;
        float a0 = o[nt][0] * invA, a1 = o[nt][1] * invA;
        float b0 = o[nt][2] * invB, b1 = o[nt][3] * invB;
        float ha0 = __bfloat162float(__float2bfloat16_rn(a0));
        float ha1 = __bfloat162float(__float2bfloat16_rn(a1));
        float hb0 = __bfloat162float(__float2bfloat16_rn(b0));
        float hb1 = __bfloat162float(__float2bfloat16_rn(b1));
        *(uint32_t*)(Ch + baseA + c) = f2bf2(ha0, ha1);
        *(uint32_t*)(Cl + baseA + c) = f2bf2(a0 - ha0, a1 - ha1);
        *(uint32_t*)(Ch + baseB + c) = f2bf2(hb0, hb1);
        *(uint32_t*)(Cl + baseB + c) = f2bf2(b0 - hb0, b1 - hb1);
    }
}

// ---------------------------------------------------------------------------
// Launcher
// ---------------------------------------------------------------------------
extern "C" void kernel_launch(void* const* d_in, const int* in_sizes, int n_in,
                              void* d_out, int out_size)
{
    const float* hs     = (const float*)d_in[0];
    const float* gamma  = (const float*)d_in[1];
    const float* beta   = (const float*)d_in[2];
    const float* qkv_w  = (const float*)d_in[3];
    const float* qkv_b  = (const float*)d_in[4];
    const float* proj_w = (const float*)d_in[5];
    const float* proj_b = (const float*)d_in[6];
    float* out = (float*)d_out;

    void *pqkv, *pxh, *pxl, *pwqh, *pwql, *pwph, *pwpl, *pch, *pcl;
    void *pqh, *pql, *pkh, *pkl, *pvh, *pvl;
    cudaGetSymbolAddress(&pqkv, g_qkv);
    cudaGetSymbolAddress(&pxh,  g_xh);  cudaGetSymbolAddress(&pxl,  g_xl);
    cudaGetSymbolAddress(&pwqh, g_wqh); cudaGetSymbolAddress(&pwql, g_wql);
    cudaGetSymbolAddress(&pwph, g_wph); cudaGetSymbolAddress(&pwpl, g_wpl);
    cudaGetSymbolAddress(&pch,  g_ch);  cudaGetSymbolAddress(&pcl,  g_cl);
    cudaGetSymbolAddress(&pqh,  g_qhh); cudaGetSymbolAddress(&pql,  g_qll);
    cudaGetSymbolAddress(&pkh,  g_khh); cudaGetSymbolAddress(&pkl,  g_kll);
    cudaGetSymbolAddress(&pvh,  g_vth); cudaGetSymbolAddress(&pvl,  g_vtl);

    cudaFuncSetAttribute(mma_gemm_smem,
        cudaFuncAttributeMaxDynamicSharedMemorySize, GEMM_SMEM);
    cudaFuncSetAttribute(attn_mma_kernel,
        cudaFuncAttributeMaxDynamicSharedMemorySize, ATT_SMEM);

    // 1) LayerNorm + split
    ln_split_kernel<<<ROWS, 256>>>(hs, gamma, beta,
        (unsigned short*)pxh, (unsigned short*)pxl);

    // weight splits
    split_bf16_kernel<<<(QKVD*DMODEL/4)/256, 256>>>(qkv_w,
        (unsigned short*)pwqh, (unsigned short*)pwql, QKVD*DMODEL/4);
    split_bf16_kernel<<<(DMODEL*DMODEL/4)/256, 256>>>(proj_w,
        (unsigned short*)pwph, (unsigned short*)pwpl, DMODEL*DMODEL/4);

    // 2) QKV GEMM
    mma_gemm_smem<<<dim3(QKVD/128, ROWS/128), 128, GEMM_SMEM>>>(
        (unsigned short*)pxh, (unsigned short*)pxl,
        (unsigned short*)pwqh, (unsigned short*)pwql,
        qkv_b, (float*)pqkv, ROWS, QKVD, DMODEL);

    // 3) RoPE + relayout, V transpose
    rope_convert_kernel<<<(BATCH*S_LEN*NHEAD*32)/256, 256>>>((float*)pqkv,
        (unsigned short*)pqh, (unsigned short*)pql,
        (unsigned short*)pkh, (unsigned short*)pkl);
    v_transpose_kernel<<<dim3(S_LEN/64, BH), 256>>>((float*)pqkv,
        (unsigned short*)pvh, (unsigned short*)pvl);

    // 4) Attention (writes split-bf16 ctx)
    attn_mma_kernel<<<dim3(S_LEN/128, BH), 256, ATT_SMEM>>>(
        (unsigned short*)pqh, (unsigned short*)pql,
        (unsigned short*)pkh, (unsigned short*)pkl,
        (unsigned short*)pvh, (unsigned short*)pvl,
        (unsigned short*)pch, (unsigned short*)pcl);

    // 5) Output projection
    mma_gemm_smem<<<dim3(DMODEL/128, ROWS/128), 128, GEMM_SMEM>>>(
        (unsigned short*)pch, (unsigned short*)pcl,
        (unsigned short*)pwph, (unsigned short*)pwpl,
        proj_b, out, ROWS, DMODEL, DMODEL);
}

// round 6
// speedup vs baseline: 5.3429x; 1.0194x over previous
#include <cuda_runtime.h>
#include <cuda_bf16.h>
#include <math.h>
#include <stdint.h>

// Problem constants
#define BATCH   2
#define S_LEN   2048
#define DMODEL  1024
#define NHEAD   16
#define HDIM    64
#define QKVD    (3*DMODEL)     // 3072
#define ROWS    (BATCH*S_LEN)  // 4096
#define BH      (BATCH*NHEAD)  // 32

// Scratch (device globals: allocation-free per harness rules)
__device__ float g_qkv[ROWS * QKVD];                       // qkv fp32 (pre-rope)
__device__ unsigned short g_xh[ROWS * DMODEL],   g_xl[ROWS * DMODEL];
__device__ unsigned short g_wqh[QKVD * DMODEL],  g_wql[QKVD * DMODEL];
__device__ unsigned short g_wph[DMODEL * DMODEL],g_wpl[DMODEL * DMODEL];
__device__ unsigned short g_ch[ROWS * DMODEL],   g_cl[ROWS * DMODEL];
// head-major bf16 split q/k (post-rope) and transposed v
__device__ unsigned short g_qhh[BH * S_LEN * HDIM], g_qll[BH * S_LEN * HDIM];
__device__ unsigned short g_khh[BH * S_LEN * HDIM], g_kll[BH * S_LEN * HDIM];
__device__ unsigned short g_vth[BH * HDIM * S_LEN], g_vtl[BH * HDIM * S_LEN];

// ---------------------------------------------------------------------------
// helpers
// ---------------------------------------------------------------------------
__device__ __forceinline__ uint32_t f2bf2(float lo, float hi) {
    __nv_bfloat162 t = __floats2bfloat162_rn(lo, hi);
    return *reinterpret_cast<uint32_t*>(&t);
}
__device__ __forceinline__ uint32_t sptr(const void* p) {
    return (uint32_t)__cvta_generic_to_shared(p);
}
__device__ __forceinline__ void cp16(void* dst, const void* src) {
    asm volatile("cp.async.cg.shared.global [%0], [%1], 16;\n"
                 :: "r"(sptr(dst)), "l"(src));
}
__device__ __forceinline__ void cp_commit() { asm volatile("cp.async.commit_group;\n"); }
__device__ __forceinline__ void cp_wait0()  { asm volatile("cp.async.wait_group 0;\n"); }
__device__ __forceinline__ void cp_wait1()  { asm volatile("cp.async.wait_group 1;\n"); }

__device__ __forceinline__ void ldsm4(uint32_t* r, const void* p) {
    asm volatile("ldmatrix.sync.aligned.m8n8.x4.shared.b16 {%0,%1,%2,%3}, [%4];\n"
                 : "=r"(r[0]), "=r"(r[1]), "=r"(r[2]), "=r"(r[3]) : "r"(sptr(p)));
}
__device__ __forceinline__ void mma_bf16(float* c, const uint32_t* a, const uint32_t* b) {
    asm volatile(
        "mma.sync.aligned.m16n8k16.row.col.f32.bf16.bf16.f32 "
        "{%0,%1,%2,%3}, {%4,%5,%6,%7}, {%8,%9}, {%0,%1,%2,%3};\n"
        : "+f"(c[0]), "+f"(c[1]), "+f"(c[2]), "+f"(c[3])
        : "r"(a[0]), "r"(a[1]), "r"(a[2]), "r"(a[3]), "r"(b[0]), "r"(b[1]));
}

// ---------------------------------------------------------------------------
// 1) LayerNorm fused with split-bf16 output
// ---------------------------------------------------------------------------
__global__ void __launch_bounds__(256) ln_split_kernel(
    const float* __restrict__ x, const float* __restrict__ gamma,
    const float* __restrict__ beta, unsigned short* __restrict__ yh,
    unsigned short* __restrict__ yl)
{
    __shared__ float red_s[8], red_ss[8];
    __shared__ float sh_mean, sh_inv;
    int row = blockIdx.x;
    int tid = threadIdx.x;
    const float4* xr = (const float4*)(x + (size_t)row * DMODEL);
    float4 v = xr[tid];
    float s  = v.x + v.y + v.z + v.w;
    float ss = v.x*v.x + v.y*v.y + v.z*v.z + v.w*v.w;
    #pragma unroll
    for (int off = 16; off > 0; off >>= 1) {
        s  += __shfl_down_sync(0xffffffffu, s,  off);
        ss += __shfl_down_sync(0xffffffffu, ss, off);
    }
    int wid = tid >> 5, lane = tid & 31;
    if (lane == 0) { red_s[wid] = s; red_ss[wid] = ss; }
    __syncthreads();
    if (tid == 0) {
        float S = 0.f, SS = 0.f;
        #pragma unroll
        for (int i = 0; i < 8; ++i) { S += red_s[i]; SS += red_ss[i]; }
        float mean = S * (1.f / DMODEL);
        float var  = SS * (1.f / DMODEL) - mean * mean;
        sh_mean = mean;
        sh_inv  = rsqrtf(var + 1e-5f);
    }
    __syncthreads();
    float mean = sh_mean, inv = sh_inv;
    float4 gv = ((const float4*)gamma)[tid];
    float4 bv = ((const float4*)beta)[tid];
    float o0 = (v.x - mean) * inv * gv.x + bv.x;
    float o1 = (v.y - mean) * inv * gv.y + bv.y;
    float o2 = (v.z - mean) * inv * gv.z + bv.z;
    float o3 = (v.w - mean) * inv * gv.w + bv.w;
    float h0 = __bfloat162float(__float2bfloat16_rn(o0));
    float h1 = __bfloat162float(__float2bfloat16_rn(o1));
    float h2 = __bfloat162float(__float2bfloat16_rn(o2));
    float h3 = __bfloat162float(__float2bfloat16_rn(o3));
    uint2 hv = make_uint2(f2bf2(h0, h1), f2bf2(h2, h3));
    uint2 lv = make_uint2(f2bf2(o0 - h0, o1 - h1), f2bf2(o2 - h2, o3 - h3));
    *(uint2*)(yh + (size_t)row * DMODEL + tid * 4) = hv;
    *(uint2*)(yl + (size_t)row * DMODEL + tid * 4) = lv;
}

// ---------------------------------------------------------------------------
// split fp32 -> (hi, lo) bf16, 4 elements/thread (weights)
// ---------------------------------------------------------------------------
__global__ void __launch_bounds__(256) split_bf16_kernel(
    const float* __restrict__ x, unsigned short* __restrict__ hi,
    unsigned short* __restrict__ lo, int n4)
{
    int i = blockIdx.x * 256 + threadIdx.x;
    if (i >= n4) return;
    float4 v = ((const float4*)x)[i];
    float h0 = __bfloat162float(__float2bfloat16_rn(v.x));
    float h1 = __bfloat162float(__float2bfloat16_rn(v.y));
    float h2 = __bfloat162float(__float2bfloat16_rn(v.z));
    float h3 = __bfloat162float(__float2bfloat16_rn(v.w));
    uint2 hv = make_uint2(f2bf2(h0, h1), f2bf2(h2, h3));
    uint2 lv = make_uint2(f2bf2(v.x - h0, v.y - h1), f2bf2(v.z - h2, v.w - h3));
    *(uint2*)(hi + (size_t)i * 4) = hv;
    *(uint2*)(lo + (size_t)i * 4) = lv;
}

// ---------------------------------------------------------------------------
// 2) Smem-staged double-buffered split-bf16 MMA GEMM.
//    C[M,N] = A[M,K] @ B[N,K]^T + bias.
//    Block 128x128, BK=32, 4 warps (2x2), warp tile 64x64.
//    Pass-swept MMA order (hh sweep, hl sweep, lh sweep) to break
//    same-accumulator dependency chains. Single sync per k-iteration:
//    wait -> sync -> issue next load -> compute.
// ---------------------------------------------------------------------------
#define GPAD 40
#define GTILE (128 * GPAD)            // ushorts per tile
#define GSTAGE (4 * GTILE)            // Ah,Al,Bh,Bl
#define GEMM_SMEM (2 * GSTAGE * 2)    // bytes

__global__ void __launch_bounds__(128) mma_gemm_smem(
    const unsigned short* __restrict__ Ahg, const unsigned short* __restrict__ Alg,
    const unsigned short* __restrict__ Bhg, const unsigned short* __restrict__ Blg,
    const float* __restrict__ bias, float* __restrict__ C,
    int M, int N, int K)
{
    extern __shared__ unsigned short smg[];
    int t = threadIdx.x;
    int wid = t >> 5, lane = t & 31;
    int wm = wid >> 1, wn = wid & 1;
    int g = lane >> 2, q = lane & 3;
    int mb = blockIdx.y * 128, nb = blockIdx.x * 128;

    float acc[4][8][4];
    #pragma unroll
    for (int mt = 0; mt < 4; ++mt)
        #pragma unroll
        for (int nt = 0; nt < 8; ++nt)
            #pragma unroll
            for (int e = 0; e < 4; ++e) acc[mt][nt][e] = 0.f;

    const int NKB = K >> 5;

    auto load_stage = [&](int st, int k0) {
        unsigned short* base = smg + st * GSTAGE;
        #pragma unroll
        for (int i = 0; i < 4; ++i) {
            int ch = t + i * 128;          // 0..511
            int row = ch >> 2, c = ch & 3; // c*8 bf16 within 32
            int soff = row * GPAD + c * 8;
            size_t goffA = (size_t)(mb + row) * K + k0 + c * 8;
            size_t goffB = (size_t)(nb + row) * K + k0 + c * 8;
            cp16(base + soff,             Ahg + goffA);
            cp16(base + GTILE + soff,     Alg + goffA);
            cp16(base + 2 * GTILE + soff, Bhg + goffB);
            cp16(base + 3 * GTILE + soff, Blg + goffB);
        }
        cp_commit();
    };

    load_stage(0, 0);

    for (int kb = 0; kb < NKB; ++kb) {
        cp_wait0();          // only group kb outstanding here
        __syncthreads();     // publish stage kb; fence stage (kb+1)&1 readers
        if (kb + 1 < NKB) load_stage((kb + 1) & 1, (kb + 1) << 5);

        unsigned short* base = smg + (kb & 1) * GSTAGE;
        unsigned short* sAh = base;
        unsigned short* sAl = base + GTILE;
        unsigned short* sBh = base + 2 * GTILE;
        unsigned short* sBl = base + 3 * GTILE;

        #pragma unroll
        for (int kk = 0; kk < 2; ++kk) {
            uint32_t ah[4][4], al[4][4];
            #pragma unroll
            for (int mt = 0; mt < 4; ++mt) {
                int r = wm * 64 + mt * 16 + (lane & 15);
                int c = kk * 16 + (lane >> 4) * 8;
                ldsm4(ah[mt], sAh + r * GPAD + c);
                ldsm4(al[mt], sAl + r * GPAD + c);
            }
            uint32_t bh2[8][2], bl2[8][2];
            #pragma unroll
            for (int p = 0; p < 4; ++p) {
                int r = wn * 64 + p * 16 + ((lane >> 4) & 1) * 8 + (lane & 7);
                int c = kk * 16 + ((lane >> 3) & 1) * 8;
                uint32_t tmp[4];
                ldsm4(tmp, sBh + r * GPAD + c);
                bh2[2*p][0] = tmp[0]; bh2[2*p][1] = tmp[1];
                bh2[2*p+1][0] = tmp[2]; bh2[2*p+1][1] = tmp[3];
                ldsm4(tmp, sBl + r * GPAD + c);
                bl2[2*p][0] = tmp[0]; bl2[2*p][1] = tmp[1];
                bl2[2*p+1][0] = tmp[2]; bl2[2*p+1][1] = tmp[3];
            }
            // pass sweeps: same-acc reuse distance = 32 MMAs
            #pragma unroll
            for (int mt = 0; mt < 4; ++mt)
                #pragma unroll
                for (int nt = 0; nt < 8; ++nt)
                    mma_bf16(acc[mt][nt], ah[mt], bh2[nt]);
            #pragma unroll
            for (int mt = 0; mt < 4; ++mt)
                #pragma unroll
                for (int nt = 0; nt < 8; ++nt)
                    mma_bf16(acc[mt][nt], ah[mt], bl2[nt]);
            #pragma unroll
            for (int mt = 0; mt < 4; ++mt)
                #pragma unroll
                for (int nt = 0; nt < 8; ++nt)
                    mma_bf16(acc[mt][nt], al[mt], bh2[nt]);
        }
    }

    #pragma unroll
    for (int mt = 0; mt < 4; ++mt) {
        #pragma unroll
        for (int nt = 0; nt < 8; ++nt) {
            int r = mb + wm * 64 + mt * 16 + g;
            int c = nb + wn * 64 + nt * 8 + q * 2;
            float b0 = bias[c], b1 = bias[c + 1];
            float2 v0; v0.x = acc[mt][nt][0] + b0; v0.y = acc[mt][nt][1] + b1;
            float2 v1; v1.x = acc[mt][nt][2] + b0; v1.y = acc[mt][nt][3] + b1;
            *(float2*)(C + (size_t)r * N + c)       = v0;
            *(float2*)(C + (size_t)(r + 8) * N + c) = v1;
        }
    }
}

// ---------------------------------------------------------------------------
// 3) RoPE + head-major split-bf16 relayout for Q (pre-scaled) and K.
// ---------------------------------------------------------------------------
__global__ void __launch_bounds__(256) rope_convert_kernel(
    const float* __restrict__ qkv,
    unsigned short* __restrict__ Qh, unsigned short* __restrict__ Ql,
    unsigned short* __restrict__ Kh, unsigned short* __restrict__ Kl)
{
    int idx = blockIdx.x * 256 + threadIdx.x;   // B*S*H*32
    int i  = idx & 31;
    int h  = (idx >> 5) & 15;
    int sb = idx >> 9;
    int s  = sb & (S_LEN - 1);
    int b  = sb >> 11;
    const double C = 0.28782844202394213;       // ln(10000)/32
    double ang = (double)s * exp(-C * (double)i);
    double n   = rint(ang * 0.15915494309189535); // 1/(2*pi)
    float ar   = (float)(ang - n * 6.283185307179586);
    float c  = cosf(ar);
    float sn = sinf(ar);

    size_t base = (size_t)sb * QKVD + h * (3 * HDIM);
    float q1 = qkv[base + i],      q2 = qkv[base + 32 + i];
    float k1 = qkv[base + 64 + i], k2 = qkv[base + 96 + i];
    float qo1 = (q1 * c - q2 * sn) * 0.125f;
    float qo2 = (q2 * c + q1 * sn) * 0.125f;
    float ko1 = k1 * c - k2 * sn;
    float ko2 = k2 * c + k1 * sn;

    size_t dst = ((size_t)(b * NHEAD + h) * S_LEN + s) * HDIM;
    float hq1 = __bfloat162float(__float2bfloat16_rn(qo1));
    float hq2 = __bfloat162float(__float2bfloat16_rn(qo2));
    float hk1 = __bfloat162float(__float2bfloat16_rn(ko1));
    float hk2 = __bfloat162float(__float2bfloat16_rn(ko2));
    Qh[dst + i]      = __bfloat16_as_ushort(__float2bfloat16_rn(qo1));
    Qh[dst + 32 + i] = __bfloat16_as_ushort(__float2bfloat16_rn(qo2));
    Ql[dst + i]      = __bfloat16_as_ushort(__float2bfloat16_rn(qo1 - hq1));
    Ql[dst + 32 + i] = __bfloat16_as_ushort(__float2bfloat16_rn(qo2 - hq2));
    Kh[dst + i]      = __bfloat16_as_ushort(__float2bfloat16_rn(ko1));
    Kh[dst + 32 + i] = __bfloat16_as_ushort(__float2bfloat16_rn(ko2));
    Kl[dst + i]      = __bfloat16_as_ushort(__float2bfloat16_rn(ko1 - hk1));
    Kl[dst + 32 + i] = __bfloat16_as_ushort(__float2bfloat16_rn(ko2 - hk2));
}

// ---------------------------------------------------------------------------
// 3b) V transpose + split: Vt[bh][d][s] from qkv v-part, tiled via smem.
// ---------------------------------------------------------------------------
__global__ void __launch_bounds__(256) v_transpose_kernel(
    const float* __restrict__ qkv,
    unsigned short* __restrict__ Vth, unsigned short* __restrict__ Vtl)
{
    __shared__ float tile[64][67];
    int st = blockIdx.x, bh = blockIdx.y;
    int b = bh >> 4, h = bh & 15;
    int t = threadIdx.x;
    #pragma unroll
    for (int it = 0; it < 4; ++it) {
        int id = t + it * 256;            // 0..1023
        int sl = id >> 4, f4 = id & 15;
        int sb = b * S_LEN + st * 64 + sl;
        float4 v = *(const float4*)(qkv + (size_t)sb * QKVD + h * 192 + 128 + f4 * 4);
        tile[sl][f4*4+0] = v.x; tile[sl][f4*4+1] = v.y;
        tile[sl][f4*4+2] = v.z; tile[sl][f4*4+3] = v.w;
    }
    __syncthreads();
    #pragma unroll
    for (int it = 0; it < 16; ++it) {
        int d  = it * 4 + (t >> 6);
        int sl = t & 63;
        float v = tile[sl][d];
        float hv = __bfloat162float(__float2bfloat16_rn(v));
        size_t dst = ((size_t)bh * HDIM + d) * S_LEN + st * 64 + sl;
        Vth[dst] = __bfloat16_as_ushort(__float2bfloat16_rn(v));
        Vtl[dst] = __bfloat16_as_ushort(__float2bfloat16_rn(v - hv));
    }
}

// ---------------------------------------------------------------------------
// 4) Tensor-core flash attention, double-buffered K/V, single sync per
//    iteration, pass-swept MMAs.
// ---------------------------------------------------------------------------
#define APAD 72
#define AQT (128 * APAD)   // Q tile ushorts
#define AKT (64 * APAD)    // K/V tile ushorts
#define AST (4 * AKT)      // one K/V stage: Kh,Kl,Vh,Vl
#define ATT_SMEM ((2 * AQT + 2 * AST) * 2)

__global__ void __launch_bounds__(256) attn_mma_kernel(
    const unsigned short* __restrict__ Qh, const unsigned short* __restrict__ Ql,
    const unsigned short* __restrict__ Kh, const unsigned short* __restrict__ Kl,
    const unsigned short* __restrict__ Vth, const unsigned short* __restrict__ Vtl,
    unsigned short* __restrict__ Ch, unsigned short* __restrict__ Cl)
{
    extern __shared__ unsigned short sma[];
    unsigned short* sQh = sma;
    unsigned short* sQl = sma + AQT;
    unsigned short* sKV = sma + 2 * AQT;   // 2 stages of [Kh|Kl|Vh|Vl]

    int qt = blockIdx.x, bh = blockIdx.y;
    int b = bh >> 4, h = bh & 15;
    int t = threadIdx.x;
    int w = t >> 5, lane = t & 31;
    int g = lane >> 2, q = lane & 3;

    auto load_kv = [&](int st, int kt) {
        unsigned short* sg = sKV + st * AST;
        size_t kbase = ((size_t)bh * S_LEN + kt * 64) * HDIM;
        #pragma unroll
        for (int i = 0; i < 2; ++i) {
            int ch = t + i * 256;     // 0..511
            int row = ch >> 3, c = ch & 7;
            int soff = row * APAD + c * 8;
            cp16(sg + soff,           Kh + kbase + row * 64 + c * 8);
            cp16(sg + AKT + soff,     Kl + kbase + row * 64 + c * 8);
            size_t vsrc = ((size_t)bh * HDIM + row) * S_LEN + kt * 64 + c * 8;
            cp16(sg + 2 * AKT + soff, Vth + vsrc);
            cp16(sg + 3 * AKT + soff, Vtl + vsrc);
        }
        cp_commit();
    };

    // prologue: stage Q (group 0), prefetch kv tile 0 (group 1)
    size_t qbase = ((size_t)bh * S_LEN + qt * 128) * HDIM;
    #pragma unroll
    for (int i = 0; i < 4; ++i) {
        int ch = t + i * 256;             // 0..1023
        int row = ch >> 3, c = ch & 7;
        cp16(sQh + row * APAD + c * 8, Qh + qbase + row * 64 + c * 8);
        cp16(sQl + row * APAD + c * 8, Ql + qbase + row * 64 + c * 8);
    }
    cp_commit();
    load_kv(0, 0);
    cp_wait1();          // Q arrived (kv0 may still be in flight)
    __syncthreads();

    uint32_t qfh[4][4], qfl[4][4];
    #pragma unroll
    for (int kk = 0; kk < 4; ++kk) {
        int r = w * 16 + (lane & 15);
        int c = kk * 16 + (lane >> 4) * 8;
        ldsm4(qfh[kk], sQh + r * APAD + c);
        ldsm4(qfl[kk], sQl + r * APAD + c);
    }

    float o[8][4];
    #pragma unroll
    for (int nt = 0; nt < 8; ++nt)
        #pragma unroll
        for (int e = 0; e < 4; ++e) o[nt][e] = 0.f;
    float mA = -1e30f, mB = -1e30f, lA = 0.f, lB = 0.f;

    int qrA = qt * 128 + w * 16 + g;
    int qmax = qt * 128 + w * 16 + 15;
    int nk = 2 * qt + 2;

    for (int kt = 0; kt < nk; ++kt) {
        cp_wait0();        // stage kt&1 copies (this thread) done
        __syncthreads();   // publish stage kt; fence stage (kt+1)&1 readers
        if (kt + 1 < nk) load_kv((kt + 1) & 1, kt + 1);

        if (kt * 64 <= qmax) {
            unsigned short* sg  = sKV + (kt & 1) * AST;
            unsigned short* sKh_ = sg;
            unsigned short* sKl_ = sg + AKT;
            unsigned short* sVh_ = sg + 2 * AKT;
            unsigned short* sVl_ = sg + 3 * AKT;

            float s_acc[8][4];
            #pragma unroll
            for (int nt = 0; nt < 8; ++nt)
                #pragma unroll
                for (int e = 0; e < 4; ++e) s_acc[nt][e] = 0.f;

            #pragma unroll
            for (int kk = 0; kk < 4; ++kk) {
                uint32_t bh2[8][2], bl2[8][2];
                #pragma unroll
                for (int p = 0; p < 4; ++p) {
                    int r = p * 16 + ((lane >> 4) & 1) * 8 + (lane & 7);
                    int c = kk * 16 + ((lane >> 3) & 1) * 8;
                    uint32_t tmp[4];
                    ldsm4(tmp, sKh_ + r * APAD + c);
                    bh2[2*p][0] = tmp[0]; bh2[2*p][1] = tmp[1];
                    bh2[2*p+1][0] = tmp[2]; bh2[2*p+1][1] = tmp[3];
                    ldsm4(tmp, sKl_ + r * APAD + c);
                    bl2[2*p][0] = tmp[0]; bl2[2*p][1] = tmp[1];
                    bl2[2*p+1][0] = tmp[2]; bl2[2*p+1][1] = tmp[3];
                }
                // pass sweeps: break same-acc chains
                #pragma unroll
                for (int nt = 0; nt < 8; ++nt)
                    mma_bf16(s_acc[nt], qfh[kk], bh2[nt]);
                #pragma unroll
                for (int nt = 0; nt < 8; ++nt)
                    mma_bf16(s_acc[nt], qfh[kk], bl2[nt]);
                #pragma unroll
                for (int nt = 0; nt < 8; ++nt)
                    mma_bf16(s_acc[nt], qfl[kk], bh2[nt]);
            }

            int kb0 = kt * 64;
            if (kb0 + 63 > qrA) {
                #pragma unroll
                for (int nt = 0; nt < 8; ++nt) {
                    int colb = kb0 + nt * 8 + 2 * q;
                    if (colb     > qrA)     s_acc[nt][0] = -1e30f;
                    if (colb + 1 > qrA)     s_acc[nt][1] = -1e30f;
                    if (colb     > qrA + 8) s_acc[nt][2] = -1e30f;
                    if (colb + 1 > qrA + 8) s_acc[nt][3] = -1e30f;
                }
            }

            float mxA = -1e30f, mxB = -1e30f;
            #pragma unroll
            for (int nt = 0; nt < 8; ++nt) {
                mxA = fmaxf(mxA, fmaxf(s_acc[nt][0], s_acc[nt][1]));
                mxB = fmaxf(mxB, fmaxf(s_acc[nt][2], s_acc[nt][3]));
            }
            mxA = fmaxf(mxA, __shfl_xor_sync(0xffffffffu, mxA, 1));
            mxA = fmaxf(mxA, __shfl_xor_sync(0xffffffffu, mxA, 2));
            mxB = fmaxf(mxB, __shfl_xor_sync(0xffffffffu, mxB, 1));
            mxB = fmaxf(mxB, __shfl_xor_sync(0xffffffffu, mxB, 2));
            float mnA = fmaxf(mA, mxA), mnB = fmaxf(mB, mxB);
            float corrA = __expf(mA - mnA), corrB = __expf(mB - mnB);
            float psA = 0.f, psB = 0.f;
            #pragma unroll
            for (int nt = 0; nt < 8; ++nt) {
                s_acc[nt][0] = __expf(s_acc[nt][0] - mnA); psA += s_acc[nt][0];
                s_acc[nt][1] = __expf(s_acc[nt][1] - mnA); psA += s_acc[nt][1];
                s_acc[nt][2] = __expf(s_acc[nt][2] - mnB); psB += s_acc[nt][2];
                s_acc[nt][3] = __expf(s_acc[nt][3] - mnB); psB += s_acc[nt][3];
            }
            psA += __shfl_xor_sync(0xffffffffu, psA, 1);
            psA += __shfl_xor_sync(0xffffffffu, psA, 2);
            psB += __shfl_xor_sync(0xffffffffu, psB, 1);
            psB += __shfl_xor_sync(0xffffffffu, psB, 2);
            lA = lA * corrA + psA;  mA = mnA;
            lB = lB * corrB + psB;  mB = mnB;
            #pragma unroll
            for (int nt = 0; nt < 8; ++nt) {
                o[nt][0] *= corrA; o[nt][1] *= corrA;
                o[nt][2] *= corrB; o[nt][3] *= corrB;
            }

            #pragma unroll
            for (int kk = 0; kk < 4; ++kk) {
                int n0 = 2 * kk, n1 = 2 * kk + 1;
                uint32_t ph[4], pl[4];
                ph[0] = f2bf2(s_acc[n0][0], s_acc[n0][1]);
                ph[1] = f2bf2(s_acc[n0][2], s_acc[n0][3]);
                ph[2] = f2bf2(s_acc[n1][0], s_acc[n1][1]);
                ph[3] = f2bf2(s_acc[n1][2], s_acc[n1][3]);
                {
                    float r00 = s_acc[n0][0] - __bfloat162float(__float2bfloat16_rn(s_acc[n0][0]));
                    float r01 = s_acc[n0][1] - __bfloat162float(__float2bfloat16_rn(s_acc[n0][1]));
                    float r02 = s_acc[n0][2] - __bfloat162float(__float2bfloat16_rn(s_acc[n0][2]));
                    float r03 = s_acc[n0][3] - __bfloat162float(__float2bfloat16_rn(s_acc[n0][3]));
                    float r10 = s_acc[n1][0] - __bfloat162float(__float2bfloat16_rn(s_acc[n1][0]));
                    float r11 = s_acc[n1][1] - __bfloat162float(__float2bfloat16_rn(s_acc[n1][1]));
                    float r12 = s_acc[n1][2] - __bfloat162float(__float2bfloat16_rn(s_acc[n1][2]));
                    float r13 = s_acc[n1][3] - __bfloat162float(__float2bfloat16_rn(s_acc[n1][3]));
                    pl[0] = f2bf2(r00, r01); pl[1] = f2bf2(r02, r03);
                    pl[2] = f2bf2(r10, r11); pl[3] = f2bf2(r12, r13);
                }
                uint32_t vh2[8][2], vl2[8][2];
                #pragma unroll
                for (int p = 0; p < 4; ++p) {
                    int r = p * 16 + ((lane >> 4) & 1) * 8 + (lane & 7);
                    int c = kk * 16 + ((lane >> 3) & 1) * 8;
                    uint32_t tmp[4];
                    ldsm4(tmp, sVh_ + r * APAD + c);
                    vh2[2*p][0] = tmp[0]; vh2[2*p][1] = tmp[1];
                    vh2[2*p+1][0] = tmp[2]; vh2[2*p+1][1] = tmp[3];
                    ldsm4(tmp, sVl_ + r * APAD + c);
                    vl2[2*p][0] = tmp[0]; vl2[2*p][1] = tmp[1];
                    vl2[2*p+1][0] = tmp[2]; vl2[2*p+1][1] = tmp[3];
                }
                // pass sweeps (o chains across kk are long-distance anyway)
                #pragma unroll
                for (int nt = 0; nt < 8; ++nt)
                    mma_bf16(o[nt], ph, vh2[nt]);
                #pragma unroll
                for (int nt = 0; nt < 8; ++nt)
                    mma_bf16(o[nt], ph, vl2[nt]);
                #pragma unroll
                for (int nt = 0; nt < 8; ++nt)
                    mma_bf16(o[nt], pl, vh2[nt]);
            }
        }
    }

    float invA = 1.f / lA, invB = 1.f / lB;
    int rowA = qt * 128 + w * 16 + g;
    size_t baseA = ((size_t)(b * S_LEN + rowA)) * DMODEL + h * HDIM;
    size_t baseB = baseA + (size_t)8 * DMODEL;
    #pragma unroll
    for (int nt = 0; nt < 8; ++nt) {
        int c = nt * 8 + 2 * q;
        float a0 = o[nt][0] * invA, a1 = o[nt][1] * invA;
        float b0 = o[nt][2] * invB, b1 = o[nt][3] * invB;
        float ha0 = __bfloat162float(__float2bfloat16_rn(a0));
        float ha1 = __bfloat162float(__float2bfloat16_rn(a1));
        float hb0 = __bfloat162float(__float2bfloat16_rn(b0));
        float hb1 = __bfloat162float(__float2bfloat16_rn(b1));
        *(uint32_t*)(Ch + baseA + c) = f2bf2(ha0, ha1);
        *(uint32_t*)(Cl + baseA + c) = f2bf2(a0 - ha0, a1 - ha1);
        *(uint32_t*)(Ch + baseB + c) = f2bf2(hb0, hb1);
        *(uint32_t*)(Cl + baseB + c) = f2bf2(b0 - hb0, b1 - hb1);
    }
}

// ---------------------------------------------------------------------------
// Launcher
// ---------------------------------------------------------------------------
extern "C" void kernel_launch(void* const* d_in, const int* in_sizes, int n_in,
                              void* d_out, int out_size)
{
    const float* hs     = (const float*)d_in[0];
    const float* gamma  = (const float*)d_in[1];
    const float* beta   = (const float*)d_in[2];
    const float* qkv_w  = (const float*)d_in[3];
    const float* qkv_b  = (const float*)d_in[4];
    const float* proj_w = (const float*)d_in[5];
    const float* proj_b = (const float*)d_in[6];
    float* out = (float*)d_out;

    void *pqkv, *pxh, *pxl, *pwqh, *pwql, *pwph, *pwpl, *pch, *pcl;
    void *pqh, *pql, *pkh, *pkl, *pvh, *pvl;
    cudaGetSymbolAddress(&pqkv, g_qkv);
    cudaGetSymbolAddress(&pxh,  g_xh);  cudaGetSymbolAddress(&pxl,  g_xl);
    cudaGetSymbolAddress(&pwqh, g_wqh); cudaGetSymbolAddress(&pwql, g_wql);
    cudaGetSymbolAddress(&pwph, g_wph); cudaGetSymbolAddress(&pwpl, g_wpl);
    cudaGetSymbolAddress(&pch,  g_ch);  cudaGetSymbolAddress(&pcl,  g_cl);
    cudaGetSymbolAddress(&pqh,  g_qhh); cudaGetSymbolAddress(&pql,  g_qll);
    cudaGetSymbolAddress(&pkh,  g_khh); cudaGetSymbolAddress(&pkl,  g_kll);
    cudaGetSymbolAddress(&pvh,  g_vth); cudaGetSymbolAddress(&pvl,  g_vtl);

    cudaFuncSetAttribute(mma_gemm_smem,
        cudaFuncAttributeMaxDynamicSharedMemorySize, GEMM_SMEM);
    cudaFuncSetAttribute(attn_mma_kernel,
        cudaFuncAttributeMaxDynamicSharedMemorySize, ATT_SMEM);

    // 1) LayerNorm + split
    ln_split_kernel<<<ROWS, 256>>>(hs, gamma, beta,
        (unsigned short*)pxh, (unsigned short*)pxl);

    // weight splits
    split_bf16_kernel<<<(QKVD*DMODEL/4)/256, 256>>>(qkv_w,
        (unsigned short*)pwqh, (unsigned short*)pwql, QKVD*DMODEL/4);
    split_bf16_kernel<<<(DMODEL*DMODEL/4)/256, 256>>>(proj_w,
        (unsigned short*)pwph, (unsigned short*)pwpl, DMODEL*DMODEL/4);

    // 2) QKV GEMM
    mma_gemm_smem<<<dim3(QKVD/128, ROWS/128), 128, GEMM_SMEM>>>(
        (unsigned short*)pxh, (unsigned short*)pxl,
        (unsigned short*)pwqh, (unsigned short*)pwql,
        qkv_b, (float*)pqkv, ROWS, QKVD, DMODEL);

    // 3) RoPE + relayout, V transpose
    rope_convert_kernel<<<(BATCH*S_LEN*NHEAD*32)/256, 256>>>((float*)pqkv,
        (unsigned short*)pqh, (unsigned short*)pql,
        (unsigned short*)pkh, (unsigned short*)pkl);
    v_transpose_kernel<<<dim3(S_LEN/64, BH), 256>>>((float*)pqkv,
        (unsigned short*)pvh, (unsigned short*)pvl);

    // 4) Attention (writes split-bf16 ctx)
    attn_mma_kernel<<<dim3(S_LEN/128, BH), 256, ATT_SMEM>>>(
        (unsigned short*)pqh, (unsigned short*)pql,
        (unsigned short*)pkh, (unsigned short*)pkl,
        (unsigned short*)pvh, (unsigned short*)pvl,
        (unsigned short*)pch, (unsigned short*)pcl);

    // 5) Output projection
    mma_gemm_smem<<<dim3(DMODEL/128, ROWS/128), 128, GEMM_SMEM>>>(
        (unsigned short*)pch, (unsigned short*)pcl,
        (unsigned short*)pwph, (unsigned short*)pwpl,
        proj_b, out, ROWS, DMODEL, DMODEL);
}